// round 2
// baseline (speedup 1.0000x reference)
#include <cuda_runtime.h>
#include <math.h>

#define B_   64
#define N_   197
#define C_   768
#define H_   12
#define D_   64
#define FF_  3072
#define DEPTH_ 12
#define M_   (B_ * N_)       // 12608 tokens
#define NN_  (N_ * N_)       // 38809

// ---------------- scratch (device globals; no runtime alloc allowed) ----------------
__device__ float g_z[M_ * C_];                       // LN output          (38.7 MB)
__device__ float g_qkv[(size_t)M_ * 3 * C_];         // QKV               (116 MB)
__device__ float g_scores[(size_t)B_ * H_ * NN_];    // attn scores       (119 MB)
__device__ float g_o[M_ * C_];                       // attn output       (38.7 MB)
__device__ float g_mlp[(size_t)M_ * FF_];            // MLP hidden        (155 MB)
__device__ float g_bias[H_ * NN_];                   // rel-pos bias      (1.9 MB)

// ---------------- helpers ----------------
__device__ __forceinline__ float warp_sum(float v) {
#pragma unroll
    for (int o = 16; o > 0; o >>= 1) v += __shfl_xor_sync(0xffffffffu, v, o);
    return v;
}

// ---------------- LayerNorm: one block per token row (C=768 = 3*256) ----------------
__global__ __launch_bounds__(256) void ln_kernel(const float* __restrict__ x,
                                                 const float* __restrict__ s,
                                                 const float* __restrict__ bsh,
                                                 float* __restrict__ z) {
    int row = blockIdx.x;
    const float* xr = x + (size_t)row * C_;
    float v[3], sum = 0.f, sq = 0.f;
#pragma unroll
    for (int i = 0; i < 3; i++) {
        v[i] = xr[threadIdx.x + i * 256];
        sum += v[i];
        sq  += v[i] * v[i];
    }
    sum = warp_sum(sum);
    sq  = warp_sum(sq);
    __shared__ float sh1[8], sh2[8];
    int w = threadIdx.x >> 5, lane = threadIdx.x & 31;
    if (lane == 0) { sh1[w] = sum; sh2[w] = sq; }
    __syncthreads();
    if (w == 0) {
        float a  = (lane < 8) ? sh1[lane] : 0.f;
        float b2 = (lane < 8) ? sh2[lane] : 0.f;
        a = warp_sum(a); b2 = warp_sum(b2);
        if (lane == 0) { sh1[0] = a; sh2[0] = b2; }
    }
    __syncthreads();
    float mean = sh1[0] * (1.f / C_);
    float var  = sh2[0] * (1.f / C_) - mean * mean;
    float r    = rsqrtf(var + 1e-5f);
#pragma unroll
    for (int i = 0; i < 3; i++) {
        int c = threadIdx.x + i * 256;
        z[(size_t)row * C_ + c] = (v[i] - mean) * r * s[c] + bsh[c];
    }
}

// ---------------- tiled SGEMM: out[M,Nc] = A[M,K] @ W[Nc,K]^T (+ epilogue) ----------
// BM=64, BN=128, BK=16, 256 threads, 4x8 per thread. All dims divide exactly.
// MODE 0: out = acc + concat(q_bias, 0, v_bias)[col]          (b0=q_bias, b1=v_bias)
// MODE 1: out += b1[col] * (acc + b0[col])                    (residual + layer scale)
// MODE 2: out = gelu(acc + b0[col])  exact gelu = x*Phi(x)
template <int MODE>
__global__ __launch_bounds__(256) void gemm_kernel(const float* __restrict__ A,
                                                   const float* __restrict__ W,
                                                   float* __restrict__ out,
                                                   const float* __restrict__ b0,
                                                   const float* __restrict__ b1,
                                                   int Nc, int K) {
    __shared__ float As[16][68];    // padded: (kk*68+ty*4)*4B stays 16B aligned
    __shared__ float Bs[16][132];
    const int t  = threadIdx.x;
    const int tx = t & 15, ty = t >> 4;
    const int m0 = blockIdx.y * 64;
    const int n0 = blockIdx.x * 128;
    const int la = t >> 2;           // 0..63
    const int lk = (t & 3) << 2;     // 0,4,8,12
    const float* Ap  = A + (size_t)(m0 + la) * K + lk;
    const float* Wp0 = W + (size_t)(n0 + la) * K + lk;
    const float* Wp1 = W + (size_t)(n0 + 64 + la) * K + lk;
    float acc[4][8] = {};
    for (int k0 = 0; k0 < K; k0 += 16) {
        float4 av  = *(const float4*)(Ap + k0);
        float4 bv0 = *(const float4*)(Wp0 + k0);
        float4 bv1 = *(const float4*)(Wp1 + k0);
        As[lk + 0][la] = av.x;  As[lk + 1][la] = av.y;
        As[lk + 2][la] = av.z;  As[lk + 3][la] = av.w;
        Bs[lk + 0][la] = bv0.x; Bs[lk + 1][la] = bv0.y;
        Bs[lk + 2][la] = bv0.z; Bs[lk + 3][la] = bv0.w;
        Bs[lk + 0][la + 64] = bv1.x; Bs[lk + 1][la + 64] = bv1.y;
        Bs[lk + 2][la + 64] = bv1.z; Bs[lk + 3][la + 64] = bv1.w;
        __syncthreads();
#pragma unroll
        for (int kk = 0; kk < 16; kk++) {
            float a[4], bb[8];
            *(float4*)a        = *(const float4*)&As[kk][ty * 4];
            *(float4*)bb       = *(const float4*)&Bs[kk][tx * 8];
            *(float4*)(bb + 4) = *(const float4*)&Bs[kk][tx * 8 + 4];
#pragma unroll
            for (int i = 0; i < 4; i++)
#pragma unroll
                for (int j = 0; j < 8; j++)
                    acc[i][j] = fmaf(a[i], bb[j], acc[i][j]);
        }
        __syncthreads();
    }
#pragma unroll
    for (int i = 0; i < 4; i++) {
        int row = m0 + ty * 4 + i;
#pragma unroll
        for (int j = 0; j < 8; j++) {
            int col = n0 + tx * 8 + j;
            float v = acc[i][j];
            size_t oidx = (size_t)row * Nc + col;
            if (MODE == 0) {
                float bias = (col < C_) ? b0[col] : ((col < 2 * C_) ? 0.f : b1[col - 2 * C_]);
                out[oidx] = v + bias;
            } else if (MODE == 1) {
                out[oidx] += b1[col] * (v + b0[col]);
            } else {
                float xg = v + b0[col];
                out[oidx] = xg * normcdff(xg);   // exact gelu
            }
        }
    }
}

// ---------------- relative position bias precompute: bias[h][n][m] ----------------
__global__ void relbias_kernel(const float* __restrict__ table, const int* __restrict__ ridx) {
    int i = blockIdx.x * 256 + threadIdx.x;
    if (i < NN_) {
        int id = ridx[i];
#pragma unroll
        for (int h = 0; h < H_; h++) g_bias[h * NN_ + i] = table[id * H_ + h];
    }
}

// ---------------- scores = scale*Q@K^T + bias, one block per (b,h) ----------------
__global__ __launch_bounds__(256) void scores_kernel(const float* __restrict__ qkv) {
    extern __shared__ float sm[];
    float* Qs = sm;              // [197][64], q pre-scaled
    float* Kt = sm + N_ * D_;    // [64][200]  (K transposed, padded pitch)
    int bh = blockIdx.x;
    int b = bh / H_, h = bh % H_;
    const float* base = qkv + (size_t)b * N_ * (3 * C_);
    int t = threadIdx.x;
    for (int idx = t; idx < N_ * D_; idx += 256) {
        int n = idx >> 6, d = idx & 63;
        Qs[idx]          = base[n * (3 * C_) + h * D_ + d] * 0.125f;      // D^-0.5
        Kt[d * 200 + n]  = base[n * (3 * C_) + C_ + h * D_ + d];
    }
    __syncthreads();
    int w = t >> 5, lane = t & 31;
    float* srow       = g_scores + (size_t)bh * NN_;
    const float* brow = g_bias + h * NN_;
    for (int n = w; n < N_; n += 8) {
        const float* q = Qs + n * 64;
        for (int m0 = lane; m0 < N_; m0 += 64) {
            int m1 = m0 + 32;
            bool two = (m1 < N_);
            int m1r = two ? m1 : m0;
            float a0 = 0.f, a1 = 0.f;
#pragma unroll
            for (int kk = 0; kk < 64; kk++) {
                float qv = q[kk];
                a0 = fmaf(qv, Kt[kk * 200 + m0], a0);
                a1 = fmaf(qv, Kt[kk * 200 + m1r], a1);
            }
            srow[n * N_ + m0] = a0 + brow[n * N_ + m0];
            if (two) srow[n * N_ + m1] = a1 + brow[n * N_ + m1];
        }
    }
}

// ---------------- row softmax over 197 cols, one warp per row ----------------
__global__ __launch_bounds__(256) void softmax_kernel() {
    int row  = blockIdx.x * 8 + (threadIdx.x >> 5);
    int lane = threadIdx.x & 31;
    float* p = g_scores + (size_t)row * N_;
    float v[7], mx = -1e30f;
#pragma unroll
    for (int i = 0; i < 7; i++) {
        int c = lane + i * 32;
        v[i] = (c < N_) ? p[c] : -1e30f;
        mx = fmaxf(mx, v[i]);
    }
#pragma unroll
    for (int o = 16; o > 0; o >>= 1) mx = fmaxf(mx, __shfl_xor_sync(0xffffffffu, mx, o));
    float s = 0.f;
#pragma unroll
    for (int i = 0; i < 7; i++) { v[i] = expf(v[i] - mx); s += v[i]; }
    s = warp_sum(s);
    float inv = 1.f / s;
#pragma unroll
    for (int i = 0; i < 7; i++) {
        int c = lane + i * 32;
        if (c < N_) p[c] = v[i] * inv;
    }
}

// ---------------- o = scores @ V, one block per (b,h) ----------------
__global__ __launch_bounds__(256) void av_kernel(const float* __restrict__ qkv,
                                                 float* __restrict__ o) {
    extern __shared__ float sm[];
    float* Vs = sm;  // [197][64]
    int bh = blockIdx.x;
    int b = bh / H_, h = bh % H_;
    const float* base = qkv + (size_t)b * N_ * (3 * C_);
    int t = threadIdx.x;
    for (int idx = t; idx < N_ * D_; idx += 256) {
        int m = idx >> 6, d = idx & 63;
        Vs[idx] = base[m * (3 * C_) + 2 * C_ + h * D_ + d];
    }
    __syncthreads();
    int r = t >> 6, d = t & 63;
    const float* sbase = g_scores + (size_t)bh * NN_;
    for (int n = r; n < N_; n += 8) {
        int n2 = n + 4;
        bool two = (n2 < N_);
        const float* s0 = sbase + n * N_;
        const float* s1 = sbase + (two ? n2 : n) * N_;
        float a0 = 0.f, a1 = 0.f;
        for (int m = 0; m < N_; m++) {
            float vv = Vs[m * 64 + d];
            a0 = fmaf(__ldg(s0 + m), vv, a0);
            a1 = fmaf(__ldg(s1 + m), vv, a1);
        }
        o[(size_t)(b * N_ + n) * C_ + h * D_ + d] = a0;
        if (two) o[(size_t)(b * N_ + n2) * C_ + h * D_ + d] = a1;
    }
}

// ---------------- launch ----------------
extern "C" void kernel_launch(void* const* d_in, const int* in_sizes, int n_in,
                              void* d_out, int out_size) {
    const float* x      = (const float*)d_in[0];
    const float* qkv_w  = (const float*)d_in[1];
    const float* q_bias = (const float*)d_in[2];
    const float* v_bias = (const float*)d_in[3];
    const float* proj_w = (const float*)d_in[4];
    const float* proj_b = (const float*)d_in[5];
    const float* ln1_s  = (const float*)d_in[6];
    const float* ln1_b  = (const float*)d_in[7];
    const float* ln2_s  = (const float*)d_in[8];
    const float* ln2_b  = (const float*)d_in[9];
    const float* fc1_w  = (const float*)d_in[10];
    const float* fc1_b  = (const float*)d_in[11];
    const float* fc2_w  = (const float*)d_in[12];
    const float* fc2_b  = (const float*)d_in[13];
    const float* gamma1 = (const float*)d_in[14];
    const float* gamma2 = (const float*)d_in[15];
    const float* rtab   = (const float*)d_in[16];
    const int*   ridx   = (const int*)d_in[17];
    float* h = (float*)d_out;   // hidden state lives in d_out (in-place residuals)

    void *pz, *pqkv, *po, *pmlp;
    cudaGetSymbolAddress(&pz, g_z);
    cudaGetSymbolAddress(&pqkv, g_qkv);
    cudaGetSymbolAddress(&po, g_o);
    cudaGetSymbolAddress(&pmlp, g_mlp);
    float* z    = (float*)pz;
    float* qkvb = (float*)pqkv;
    float* o    = (float*)po;
    float* mlp  = (float*)pmlp;

    const int scores_smem = (N_ * D_ + 64 * 200) * 4;  // 101632 B
    const int av_smem     = N_ * D_ * 4;               // 50432 B
    cudaFuncSetAttribute(scores_kernel, cudaFuncAttributeMaxDynamicSharedMemorySize, scores_smem);
    cudaFuncSetAttribute(av_kernel,     cudaFuncAttributeMaxDynamicSharedMemorySize, av_smem);

    cudaMemcpyAsync(h, x, sizeof(float) * (size_t)M_ * C_, cudaMemcpyDeviceToDevice);
    relbias_kernel<<<(NN_ + 255) / 256, 256>>>(rtab, ridx);

    for (int l = 0; l < DEPTH_; l++) {
        // z = LN1(h)
        ln_kernel<<<M_, 256>>>(h, ln1_s + l * C_, ln1_b + l * C_, z);
        // qkv = z @ qkv_w^T + [qb, 0, vb]
        gemm_kernel<0><<<dim3(3 * C_ / 128, M_ / 64), 256>>>(
            z, qkv_w + (size_t)l * 3 * C_ * C_, qkvb,
            q_bias + l * C_, v_bias + l * C_, 3 * C_, C_);
        // attention
        scores_kernel<<<B_ * H_, 256, scores_smem>>>(qkvb);
        softmax_kernel<<<B_ * H_ * N_ / 8, 256>>>();
        av_kernel<<<B_ * H_, 256, av_smem>>>(qkvb, o);
        // h += g1 * (o @ proj_w^T + proj_b)
        gemm_kernel<1><<<dim3(C_ / 128, M_ / 64), 256>>>(
            o, proj_w + (size_t)l * C_ * C_, h,
            proj_b + l * C_, gamma1 + l * C_, C_, C_);
        // z = LN2(h)
        ln_kernel<<<M_, 256>>>(h, ln2_s + l * C_, ln2_b + l * C_, z);
        // mlp = gelu(z @ fc1_w^T + fc1_b)
        gemm_kernel<2><<<dim3(FF_ / 128, M_ / 64), 256>>>(
            z, fc1_w + (size_t)l * FF_ * C_, mlp,
            fc1_b + l * FF_, nullptr, FF_, C_);
        // h += g2 * (mlp @ fc2_w^T + fc2_b)
        gemm_kernel<1><<<dim3(C_ / 128, M_ / 64), 256>>>(
            mlp, fc2_w + (size_t)l * C_ * FF_, h,
            fc2_b + l * C_, gamma2 + l * C_, C_, FF_);
    }
}

// round 4
// speedup vs baseline: 3.7264x; 3.7264x over previous
#include <cuda_runtime.h>
#include <cuda_bf16.h>
#include <cstdint>
#include <cstddef>
#include <math.h>

#define B_     64
#define N_     197
#define C_     768
#define H_     12
#define D_     64
#define FF_    3072
#define DEPTH_ 12
#define M_     (B_ * N_)
#define NN_    (N_ * N_)

#define W_QKV_OFF  0
#define W_PROJ_OFF (3 * C_ * C_)
#define W_FC1_OFF  (W_PROJ_OFF + C_ * C_)
#define W_FC2_OFF  (W_FC1_OFF + FF_ * C_)
#define W_LSTRIDE  (W_FC2_OFF + C_ * FF_)

// ---------------- scratch (device globals) ----------------
__device__ __nv_bfloat16 g_z[M_ * C_];
__device__ float         g_qkv[(size_t)M_ * 3 * C_];
__device__ float         g_scores[(size_t)B_ * H_ * NN_];
__device__ __nv_bfloat16 g_o[M_ * C_];
__device__ __nv_bfloat16 g_mlp[(size_t)M_ * FF_];
__device__ float         g_bias[H_ * NN_];
__device__ __nv_bfloat16 g_wbf[(size_t)DEPTH_ * W_LSTRIDE];

// ---------------- helpers ----------------
__device__ __forceinline__ float warp_sum(float v) {
#pragma unroll
    for (int o = 16; o > 0; o >>= 1) v += __shfl_xor_sync(0xffffffffu, v, o);
    return v;
}

__device__ __forceinline__ unsigned s2u(const void* p) {
    return (unsigned)__cvta_generic_to_shared(p);
}

__device__ __forceinline__ void ldsm4(unsigned& r0, unsigned& r1, unsigned& r2, unsigned& r3,
                                      unsigned addr) {
    asm volatile("ldmatrix.sync.aligned.m8n8.x4.shared.b16 {%0,%1,%2,%3}, [%4];"
                 : "=r"(r0), "=r"(r1), "=r"(r2), "=r"(r3)
                 : "r"(addr));
}

__device__ __forceinline__ void mma16816(float* c, const unsigned* a, unsigned b0, unsigned b1) {
    asm volatile(
        "mma.sync.aligned.m16n8k16.row.col.f32.bf16.bf16.f32 "
        "{%0,%1,%2,%3}, {%4,%5,%6,%7}, {%8,%9}, {%0,%1,%2,%3};"
        : "+f"(c[0]), "+f"(c[1]), "+f"(c[2]), "+f"(c[3])
        : "r"(a[0]), "r"(a[1]), "r"(a[2]), "r"(a[3]), "r"(b0), "r"(b1));
}

// ---------------- weight fp32 -> bf16 ----------------
__global__ void cvtw_kernel(const float* __restrict__ src, int per_layer,
                            int toff, int total4) {
    int i = blockIdx.x * 256 + threadIdx.x;
    if (i >= total4) return;
    int e = i * 4;
    int l = e / per_layer;
    int w = e % per_layer;
    float4 v = *(const float4*)(src + e);
    __nv_bfloat16* d = g_wbf + (size_t)l * W_LSTRIDE + toff + w;
    d[0] = __float2bfloat16(v.x);
    d[1] = __float2bfloat16(v.y);
    d[2] = __float2bfloat16(v.z);
    d[3] = __float2bfloat16(v.w);
}

// ---------------- LayerNorm -> bf16 ----------------
__global__ __launch_bounds__(256) void ln_kernel(const float* __restrict__ x,
                                                 const float* __restrict__ s,
                                                 const float* __restrict__ bsh,
                                                 __nv_bfloat16* __restrict__ z) {
    int row = blockIdx.x;
    const float* xr = x + (size_t)row * C_;
    float v0 = xr[threadIdx.x];
    float v1 = xr[threadIdx.x + 256];
    float v2 = xr[threadIdx.x + 512];
    float sum = v0 + v1 + v2;
    float sq  = v0 * v0 + v1 * v1 + v2 * v2;
    sum = warp_sum(sum);
    sq  = warp_sum(sq);
    __shared__ float sh1[8];
    __shared__ float sh2[8];
    int w = threadIdx.x >> 5;
    int lane = threadIdx.x & 31;
    if (lane == 0) { sh1[w] = sum; sh2[w] = sq; }
    __syncthreads();
    if (w == 0) {
        float a  = (lane < 8) ? sh1[lane] : 0.f;
        float b2 = (lane < 8) ? sh2[lane] : 0.f;
        a  = warp_sum(a);
        b2 = warp_sum(b2);
        if (lane == 0) { sh1[0] = a; sh2[0] = b2; }
    }
    __syncthreads();
    float mean = sh1[0] * (1.f / C_);
    float var  = sh2[0] * (1.f / C_) - mean * mean;
    float r    = rsqrtf(var + 1e-5f);
    int c0 = threadIdx.x;
    z[(size_t)row * C_ + c0]       = __float2bfloat16((v0 - mean) * r * s[c0]       + bsh[c0]);
    z[(size_t)row * C_ + c0 + 256] = __float2bfloat16((v1 - mean) * r * s[c0 + 256] + bsh[c0 + 256]);
    z[(size_t)row * C_ + c0 + 512] = __float2bfloat16((v2 - mean) * r * s[c0 + 512] + bsh[c0 + 512]);
}

// ---------------- bf16 HMMA GEMM ----------------
// out[M,Nc] = A[M,K] @ W[Nc,K]^T + epilogue.  BM=64 BN=128 BK=32, 8 warps (2x4),
// warp tile 32x32 via m16n8k16, double-buffered smem, pitch 40 bf16 (80B).
// MODE 0: fp32 out = acc + concat(q_bias,0,v_bias)[col]
// MODE 1: fp32 out += b1[col]*(acc + b0[col])
// MODE 2: bf16 out = gelu(acc + b0[col])
#define PITCH 40
#define ASZ   (64 * PITCH)
#define BSZ   (128 * PITCH)
#define BUFE  (ASZ + BSZ)

template <int MODE>
__global__ __launch_bounds__(256) void mma_gemm(const __nv_bfloat16* __restrict__ A,
                                                const __nv_bfloat16* __restrict__ W,
                                                void* __restrict__ outv,
                                                const float* __restrict__ b0,
                                                const float* __restrict__ b1,
                                                int Nc, int K) {
    __shared__ __nv_bfloat16 smem[2 * BUFE];
    const int t    = threadIdx.x;
    const int warp = t >> 5;
    const int lane = t & 31;
    const int wm = warp >> 2;
    const int wn = warp & 3;
    const int m0 = blockIdx.y * 64;
    const int n0 = blockIdx.x * 128;

    const int ar = t >> 2;
    const int ak = (t & 3) * 8;
    const int br = t >> 1;
    const int bk = (t & 1) * 16;
    const __nv_bfloat16* Ag = A + (size_t)(m0 + ar) * K + ak;
    const __nv_bfloat16* Wg = W + (size_t)(n0 + br) * K + bk;

    const int g  = lane >> 3;
    const int rr = lane & 7;
    const unsigned aoff = (unsigned)(((wm * 32 + ((g & 1) << 3) + rr) * PITCH + ((g >> 1) << 3)) * 2);
    const unsigned boff = (unsigned)(((wn * 32 + ((g >> 1) << 3) + rr) * PITCH + ((g & 1) << 3)) * 2);
    const unsigned usm = s2u(smem);

    float acc[2][4][4];
#pragma unroll
    for (int i = 0; i < 2; i++)
#pragma unroll
        for (int j = 0; j < 4; j++)
#pragma unroll
            for (int q = 0; q < 4; q++) acc[i][j][q] = 0.f;

    uint4 av  = *(const uint4*)Ag;
    uint4 bv0 = *(const uint4*)Wg;
    uint4 bv1 = *(const uint4*)(Wg + 8);
    *(uint4*)&smem[ar * PITCH + ak]           = av;
    *(uint4*)&smem[ASZ + br * PITCH + bk]     = bv0;
    *(uint4*)&smem[ASZ + br * PITCH + bk + 8] = bv1;
    __syncthreads();

    const int nk = K / 32;
    for (int c = 0; c < nk; c++) {
        const int buf = c & 1;
        if (c + 1 < nk) {
            av  = *(const uint4*)(Ag + (c + 1) * 32);
            bv0 = *(const uint4*)(Wg + (c + 1) * 32);
            bv1 = *(const uint4*)(Wg + (c + 1) * 32 + 8);
        }
        const unsigned baseA = usm + (unsigned)(buf * (BUFE * 2));
        const unsigned baseB = baseA + (unsigned)(ASZ * 2);
#pragma unroll
        for (int s = 0; s < 2; s++) {
            unsigned a0[4], a1[4], bA[4], bB[4];
            ldsm4(a0[0], a0[1], a0[2], a0[3], baseA + aoff + s * 32);
            ldsm4(a1[0], a1[1], a1[2], a1[3], baseA + aoff + 16 * PITCH * 2 + s * 32);
            ldsm4(bA[0], bA[1], bA[2], bA[3], baseB + boff + s * 32);
            ldsm4(bB[0], bB[1], bB[2], bB[3], baseB + boff + 16 * PITCH * 2 + s * 32);
            mma16816(acc[0][0], a0, bA[0], bA[1]);
            mma16816(acc[0][1], a0, bA[2], bA[3]);
            mma16816(acc[0][2], a0, bB[0], bB[1]);
            mma16816(acc[0][3], a0, bB[2], bB[3]);
            mma16816(acc[1][0], a1, bA[0], bA[1]);
            mma16816(acc[1][1], a1, bA[2], bA[3]);
            mma16816(acc[1][2], a1, bB[0], bB[1]);
            mma16816(acc[1][3], a1, bB[2], bB[3]);
        }
        if (c + 1 < nk) {
            const int nb = buf ^ 1;
            *(uint4*)&smem[nb * BUFE + ar * PITCH + ak]           = av;
            *(uint4*)&smem[nb * BUFE + ASZ + br * PITCH + bk]     = bv0;
            *(uint4*)&smem[nb * BUFE + ASZ + br * PITCH + bk + 8] = bv1;
        }
        __syncthreads();
    }

#pragma unroll
    for (int i = 0; i < 2; i++) {
        int row = m0 + wm * 32 + i * 16 + (lane >> 2);
#pragma unroll
        for (int j = 0; j < 4; j++) {
            int col = n0 + wn * 32 + j * 8 + 2 * (lane & 3);
#pragma unroll
            for (int half = 0; half < 2; half++) {
                int r2 = row + half * 8;
                float v0 = acc[i][j][half * 2 + 0];
                float v1 = acc[i][j][half * 2 + 1];
                size_t oidx = (size_t)r2 * Nc + col;
                if (MODE == 0) {
                    float bb0;
                    float bb1;
                    if (col < C_)            bb0 = b0[col];
                    else if (col < 2 * C_)   bb0 = 0.f;
                    else                     bb0 = b1[col - 2 * C_];
                    if (col + 1 < C_)          bb1 = b0[col + 1];
                    else if (col + 1 < 2 * C_) bb1 = 0.f;
                    else                       bb1 = b1[col + 1 - 2 * C_];
                    float2* op = (float2*)((float*)outv + oidx);
                    float2 res;
                    res.x = v0 + bb0;
                    res.y = v1 + bb1;
                    *op = res;
                } else if (MODE == 1) {
                    float2* op = (float2*)((float*)outv + oidx);
                    float2 cur = *op;
                    cur.x += b1[col]     * (v0 + b0[col]);
                    cur.y += b1[col + 1] * (v1 + b0[col + 1]);
                    *op = cur;
                } else {
                    float x0 = v0 + b0[col];
                    float x1 = v1 + b0[col + 1];
                    x0 = x0 * normcdff(x0);
                    x1 = x1 * normcdff(x1);
                    __nv_bfloat162* op = (__nv_bfloat162*)((__nv_bfloat16*)outv + oidx);
                    *op = __floats2bfloat162_rn(x0, x1);
                }
            }
        }
    }
}

// ---------------- relative position bias ----------------
__global__ void relbias_kernel(const float* __restrict__ table, const int* __restrict__ ridx) {
    int i = blockIdx.x * 256 + threadIdx.x;
    if (i < NN_) {
        int id = ridx[i];
#pragma unroll
        for (int h = 0; h < H_; h++) g_bias[h * NN_ + i] = table[id * H_ + h];
    }
}

// ---------------- scores = scale*Q@K^T + bias ----------------
__global__ __launch_bounds__(512) void scores_kernel(const float* __restrict__ qkv) {
    extern __shared__ float smx[];
    float* Qs = smx;
    float* Kt = smx + N_ * D_;
    int bh = blockIdx.x;
    int b = bh / H_;
    int h = bh % H_;
    const float* base = qkv + (size_t)b * N_ * (3 * C_);
    int t = threadIdx.x;
    for (int idx = t; idx < N_ * D_; idx += 512) {
        int n = idx >> 6;
        int d = idx & 63;
        Qs[idx]         = base[n * (3 * C_) + h * D_ + d] * 0.125f;
        Kt[d * 200 + n] = base[n * (3 * C_) + C_ + h * D_ + d];
    }
    __syncthreads();
    int w = t >> 5;
    int lane = t & 31;
    float* srow       = g_scores + (size_t)bh * NN_;
    const float* brow = g_bias + h * NN_;
    for (int n = w; n < N_; n += 16) {
        const float* q = Qs + n * 64;
        for (int m0 = lane; m0 < N_; m0 += 64) {
            int m1 = m0 + 32;
            bool two = (m1 < N_);
            int m1r = two ? m1 : m0;
            float a0 = 0.f;
            float a1 = 0.f;
#pragma unroll
            for (int kk = 0; kk < 64; kk++) {
                float qv = q[kk];
                a0 = fmaf(qv, Kt[kk * 200 + m0], a0);
                a1 = fmaf(qv, Kt[kk * 200 + m1r], a1);
            }
            srow[n * N_ + m0] = a0 + brow[n * N_ + m0];
            if (two) srow[n * N_ + m1] = a1 + brow[n * N_ + m1];
        }
    }
}

// ---------------- softmax ----------------
__global__ __launch_bounds__(256) void softmax_kernel() {
    int row  = blockIdx.x * 8 + (threadIdx.x >> 5);
    int lane = threadIdx.x & 31;
    float* p = g_scores + (size_t)row * N_;
    float v[7];
    float mx = -1e30f;
#pragma unroll
    for (int i = 0; i < 7; i++) {
        int c = lane + i * 32;
        v[i] = (c < N_) ? p[c] : -1e30f;
        mx = fmaxf(mx, v[i]);
    }
#pragma unroll
    for (int o = 16; o > 0; o >>= 1) mx = fmaxf(mx, __shfl_xor_sync(0xffffffffu, mx, o));
    float s = 0.f;
#pragma unroll
    for (int i = 0; i < 7; i++) {
        v[i] = expf(v[i] - mx);
        s += v[i];
    }
    s = warp_sum(s);
    float inv = 1.f / s;
#pragma unroll
    for (int i = 0; i < 7; i++) {
        int c = lane + i * 32;
        if (c < N_) p[c] = v[i] * inv;
    }
}

// ---------------- o = scores @ V ----------------
__global__ __launch_bounds__(512) void av_kernel(const float* __restrict__ qkv,
                                                 __nv_bfloat16* __restrict__ o) {
    extern __shared__ float smx[];
    float* Vs = smx;
    int bh = blockIdx.x;
    int b = bh / H_;
    int h = bh % H_;
    const float* base = qkv + (size_t)b * N_ * (3 * C_);
    int t = threadIdx.x;
    for (int idx = t; idx < N_ * D_; idx += 512) {
        int m = idx >> 6;
        int d = idx & 63;
        Vs[idx] = base[m * (3 * C_) + 2 * C_ + h * D_ + d];
    }
    __syncthreads();
    int r = t >> 6;
    int d = t & 63;
    const float* sbase = g_scores + (size_t)bh * NN_;
    for (int n = r; n < N_; n += 16) {
        int n2 = n + 8;
        bool two = (n2 < N_);
        const float* s0 = sbase + n * N_;
        const float* s1 = sbase + (two ? n2 : n) * N_;
        float a0 = 0.f;
        float a1 = 0.f;
        for (int m = 0; m < N_; m++) {
            float vv = Vs[m * 64 + d];
            a0 = fmaf(__ldg(s0 + m), vv, a0);
            a1 = fmaf(__ldg(s1 + m), vv, a1);
        }
        o[(size_t)(b * N_ + n) * C_ + h * D_ + d] = __float2bfloat16(a0);
        if (two) o[(size_t)(b * N_ + n2) * C_ + h * D_ + d] = __float2bfloat16(a1);
    }
}

// ---------------- launch ----------------
extern "C" void kernel_launch(void* const* d_in, const int* in_sizes, int n_in,
                              void* d_out, int out_size) {
    const float* x      = (const float*)d_in[0];
    const float* qkv_w  = (const float*)d_in[1];
    const float* q_bias = (const float*)d_in[2];
    const float* v_bias = (const float*)d_in[3];
    const float* proj_w = (const float*)d_in[4];
    const float* proj_b = (const float*)d_in[5];
    const float* ln1_s  = (const float*)d_in[6];
    const float* ln1_b  = (const float*)d_in[7];
    const float* ln2_s  = (const float*)d_in[8];
    const float* ln2_b  = (const float*)d_in[9];
    const float* fc1_w  = (const float*)d_in[10];
    const float* fc1_b  = (const float*)d_in[11];
    const float* fc2_w  = (const float*)d_in[12];
    const float* fc2_b  = (const float*)d_in[13];
    const float* gamma1 = (const float*)d_in[14];
    const float* gamma2 = (const float*)d_in[15];
    const float* rtab   = (const float*)d_in[16];
    const int*   ridx   = (const int*)d_in[17];
    float* h = (float*)d_out;

    void* pz = 0;
    void* pqkv = 0;
    void* po = 0;
    void* pmlp = 0;
    void* pw = 0;
    cudaGetSymbolAddress(&pz, g_z);
    cudaGetSymbolAddress(&pqkv, g_qkv);
    cudaGetSymbolAddress(&po, g_o);
    cudaGetSymbolAddress(&pmlp, g_mlp);
    cudaGetSymbolAddress(&pw, g_wbf);
    __nv_bfloat16* z    = (__nv_bfloat16*)pz;
    float*         qkvb = (float*)pqkv;
    __nv_bfloat16* o    = (__nv_bfloat16*)po;
    __nv_bfloat16* mlp  = (__nv_bfloat16*)pmlp;
    __nv_bfloat16* wbf  = (__nv_bfloat16*)pw;

    const int scores_smem = (N_ * D_ + 64 * 200) * 4;
    const int av_smem     = N_ * D_ * 4;
    cudaFuncSetAttribute(scores_kernel, cudaFuncAttributeMaxDynamicSharedMemorySize, scores_smem);
    cudaFuncSetAttribute(av_kernel,     cudaFuncAttributeMaxDynamicSharedMemorySize, av_smem);

    cudaMemcpyAsync(h, x, sizeof(float) * (size_t)M_ * C_, cudaMemcpyDeviceToDevice);
    relbias_kernel<<<(NN_ + 255) / 256, 256>>>(rtab, ridx);

    {
        int pq = 3 * C_ * C_;
        int pp = C_ * C_;
        int p1 = FF_ * C_;
        int p2 = C_ * FF_;
        int tq = DEPTH_ * pq / 4;
        int tp = DEPTH_ * pp / 4;
        int t1 = DEPTH_ * p1 / 4;
        int t2 = DEPTH_ * p2 / 4;
        cvtw_kernel<<<(tq + 255) / 256, 256>>>(qkv_w,  pq, W_QKV_OFF,  tq);
        cvtw_kernel<<<(tp + 255) / 256, 256>>>(proj_w, pp, W_PROJ_OFF, tp);
        cvtw_kernel<<<(t1 + 255) / 256, 256>>>(fc1_w,  p1, W_FC1_OFF,  t1);
        cvtw_kernel<<<(t2 + 255) / 256, 256>>>(fc2_w,  p2, W_FC2_OFF,  t2);
    }

    for (int l = 0; l < DEPTH_; l++) {
        const __nv_bfloat16* wl = wbf + (size_t)l * W_LSTRIDE;
        ln_kernel<<<M_, 256>>>(h, ln1_s + l * C_, ln1_b + l * C_, z);
        mma_gemm<0><<<dim3(3 * C_ / 128, M_ / 64), 256>>>(
            z, wl + W_QKV_OFF, (void*)qkvb, q_bias + l * C_, v_bias + l * C_, 3 * C_, C_);
        scores_kernel<<<B_ * H_, 512, scores_smem>>>(qkvb);
        softmax_kernel<<<B_ * H_ * N_ / 8, 256>>>();
        av_kernel<<<B_ * H_, 512, av_smem>>>(qkvb, o);
        mma_gemm<1><<<dim3(C_ / 128, M_ / 64), 256>>>(
            o, wl + W_PROJ_OFF, (void*)h, proj_b + l * C_, gamma1 + l * C_, C_, C_);
        ln_kernel<<<M_, 256>>>(h, ln2_s + l * C_, ln2_b + l * C_, z);
        mma_gemm<2><<<dim3(FF_ / 128, M_ / 64), 256>>>(
            z, wl + W_FC1_OFF, (void*)mlp, fc1_b + l * FF_, (const float*)0, FF_, C_);
        mma_gemm<1><<<dim3(C_ / 128, M_ / 64), 256>>>(
            mlp, wl + W_FC2_OFF, (void*)h, fc2_b + l * C_, gamma2 + l * C_, C_, FF_);
    }
}

// round 5
// speedup vs baseline: 5.9855x; 1.6062x over previous
#include <cuda_runtime.h>
#include <cuda_bf16.h>
#include <cstdint>
#include <cstddef>
#include <math.h>

#define B_     64
#define N_     197
#define C_     768
#define H_     12
#define D_     64
#define FF_    3072
#define DEPTH_ 12
#define M_     (B_ * N_)
#define NN_    (N_ * N_)

#define W_QKV_OFF  0
#define W_PROJ_OFF (3 * C_ * C_)
#define W_FC1_OFF  (W_PROJ_OFF + C_ * C_)
#define W_FC2_OFF  (W_FC1_OFF + FF_ * C_)
#define W_LSTRIDE  (W_FC2_OFF + C_ * FF_)

// ---------------- scratch (device globals) ----------------
__device__ __nv_bfloat16 g_z[M_ * C_];
__device__ __nv_bfloat16 g_qkvb[(size_t)M_ * 3 * C_];
__device__ __nv_bfloat16 g_o[M_ * C_];
__device__ __nv_bfloat16 g_mlp[(size_t)M_ * FF_];
__device__ float         g_bias[H_ * NN_];
__device__ __nv_bfloat16 g_wbf[(size_t)DEPTH_ * W_LSTRIDE];

// ---------------- helpers ----------------
__device__ __forceinline__ float warp_sum(float v) {
#pragma unroll
    for (int o = 16; o > 0; o >>= 1) v += __shfl_xor_sync(0xffffffffu, v, o);
    return v;
}

__device__ __forceinline__ unsigned s2u(const void* p) {
    return (unsigned)__cvta_generic_to_shared(p);
}

__device__ __forceinline__ void ldsm4(unsigned& r0, unsigned& r1, unsigned& r2, unsigned& r3,
                                      unsigned addr) {
    asm volatile("ldmatrix.sync.aligned.m8n8.x4.shared.b16 {%0,%1,%2,%3}, [%4];"
                 : "=r"(r0), "=r"(r1), "=r"(r2), "=r"(r3)
                 : "r"(addr));
}

__device__ __forceinline__ void mma16816(float* c, const unsigned* a, unsigned b0, unsigned b1) {
    asm volatile(
        "mma.sync.aligned.m16n8k16.row.col.f32.bf16.bf16.f32 "
        "{%0,%1,%2,%3}, {%4,%5,%6,%7}, {%8,%9}, {%0,%1,%2,%3};"
        : "+f"(c[0]), "+f"(c[1]), "+f"(c[2]), "+f"(c[3])
        : "r"(a[0]), "r"(a[1]), "r"(a[2]), "r"(a[3]), "r"(b0), "r"(b1));
}

__device__ __forceinline__ unsigned packbf(float x, float y) {
    __nv_bfloat162 t = __floats2bfloat162_rn(x, y);
    return *(unsigned*)&t;
}

// ---------------- weight fp32 -> bf16 ----------------
__global__ void cvtw_kernel(const float* __restrict__ src, int per_layer,
                            int toff, int total4) {
    int i = blockIdx.x * 256 + threadIdx.x;
    if (i >= total4) return;
    int e = i * 4;
    int l = e / per_layer;
    int w = e % per_layer;
    float4 v = *(const float4*)(src + e);
    __nv_bfloat16* d = g_wbf + (size_t)l * W_LSTRIDE + toff + w;
    d[0] = __float2bfloat16(v.x);
    d[1] = __float2bfloat16(v.y);
    d[2] = __float2bfloat16(v.z);
    d[3] = __float2bfloat16(v.w);
}

// ---------------- LayerNorm -> bf16 ----------------
__global__ __launch_bounds__(256) void ln_kernel(const float* __restrict__ x,
                                                 const float* __restrict__ s,
                                                 const float* __restrict__ bsh,
                                                 __nv_bfloat16* __restrict__ z) {
    int row = blockIdx.x;
    const float* xr = x + (size_t)row * C_;
    float v0 = xr[threadIdx.x];
    float v1 = xr[threadIdx.x + 256];
    float v2 = xr[threadIdx.x + 512];
    float sum = v0 + v1 + v2;
    float sq  = v0 * v0 + v1 * v1 + v2 * v2;
    sum = warp_sum(sum);
    sq  = warp_sum(sq);
    __shared__ float sh1[8];
    __shared__ float sh2[8];
    int w = threadIdx.x >> 5;
    int lane = threadIdx.x & 31;
    if (lane == 0) { sh1[w] = sum; sh2[w] = sq; }
    __syncthreads();
    if (w == 0) {
        float a  = (lane < 8) ? sh1[lane] : 0.f;
        float b2 = (lane < 8) ? sh2[lane] : 0.f;
        a  = warp_sum(a);
        b2 = warp_sum(b2);
        if (lane == 0) { sh1[0] = a; sh2[0] = b2; }
    }
    __syncthreads();
    float mean = sh1[0] * (1.f / C_);
    float var  = sh2[0] * (1.f / C_) - mean * mean;
    float r    = rsqrtf(var + 1e-5f);
    int c0 = threadIdx.x;
    z[(size_t)row * C_ + c0]       = __float2bfloat16((v0 - mean) * r * s[c0]       + bsh[c0]);
    z[(size_t)row * C_ + c0 + 256] = __float2bfloat16((v1 - mean) * r * s[c0 + 256] + bsh[c0 + 256]);
    z[(size_t)row * C_ + c0 + 512] = __float2bfloat16((v2 - mean) * r * s[c0 + 512] + bsh[c0 + 512]);
}

// ---------------- bf16 HMMA GEMM ----------------
// MODE 0: bf16 out = (acc + q_bias)*0.125 | acc | acc + v_bias   (qkv, q pre-scaled)
// MODE 1: fp32 out += b1[col]*(acc + b0[col])
// MODE 2: bf16 out = gelu(acc + b0[col])
#define PITCH 40
#define ASZ   (64 * PITCH)
#define BSZ   (128 * PITCH)
#define BUFE  (ASZ + BSZ)

template <int MODE>
__global__ __launch_bounds__(256) void mma_gemm(const __nv_bfloat16* __restrict__ A,
                                                const __nv_bfloat16* __restrict__ W,
                                                void* __restrict__ outv,
                                                const float* __restrict__ b0,
                                                const float* __restrict__ b1,
                                                int Nc, int K) {
    __shared__ __nv_bfloat16 smem[2 * BUFE];
    const int t    = threadIdx.x;
    const int warp = t >> 5;
    const int lane = t & 31;
    const int wm = warp >> 2;
    const int wn = warp & 3;
    const int m0 = blockIdx.y * 64;
    const int n0 = blockIdx.x * 128;

    const int ar = t >> 2;
    const int ak = (t & 3) * 8;
    const int br = t >> 1;
    const int bk = (t & 1) * 16;
    const __nv_bfloat16* Ag = A + (size_t)(m0 + ar) * K + ak;
    const __nv_bfloat16* Wg = W + (size_t)(n0 + br) * K + bk;

    const int g  = lane >> 3;
    const int rr = lane & 7;
    const unsigned aoff = (unsigned)(((wm * 32 + ((g & 1) << 3) + rr) * PITCH + ((g >> 1) << 3)) * 2);
    const unsigned boff = (unsigned)(((wn * 32 + ((g >> 1) << 3) + rr) * PITCH + ((g & 1) << 3)) * 2);
    const unsigned usm = s2u(smem);

    float acc[2][4][4];
#pragma unroll
    for (int i = 0; i < 2; i++)
#pragma unroll
        for (int j = 0; j < 4; j++)
#pragma unroll
            for (int q = 0; q < 4; q++) acc[i][j][q] = 0.f;

    uint4 av  = *(const uint4*)Ag;
    uint4 bv0 = *(const uint4*)Wg;
    uint4 bv1 = *(const uint4*)(Wg + 8);
    *(uint4*)&smem[ar * PITCH + ak]           = av;
    *(uint4*)&smem[ASZ + br * PITCH + bk]     = bv0;
    *(uint4*)&smem[ASZ + br * PITCH + bk + 8] = bv1;
    __syncthreads();

    const int nk = K / 32;
    for (int c = 0; c < nk; c++) {
        const int buf = c & 1;
        if (c + 1 < nk) {
            av  = *(const uint4*)(Ag + (c + 1) * 32);
            bv0 = *(const uint4*)(Wg + (c + 1) * 32);
            bv1 = *(const uint4*)(Wg + (c + 1) * 32 + 8);
        }
        const unsigned baseA = usm + (unsigned)(buf * (BUFE * 2));
        const unsigned baseB = baseA + (unsigned)(ASZ * 2);
#pragma unroll
        for (int s = 0; s < 2; s++) {
            unsigned a0[4], a1[4], bA[4], bB[4];
            ldsm4(a0[0], a0[1], a0[2], a0[3], baseA + aoff + s * 32);
            ldsm4(a1[0], a1[1], a1[2], a1[3], baseA + aoff + 16 * PITCH * 2 + s * 32);
            ldsm4(bA[0], bA[1], bA[2], bA[3], baseB + boff + s * 32);
            ldsm4(bB[0], bB[1], bB[2], bB[3], baseB + boff + 16 * PITCH * 2 + s * 32);
            mma16816(acc[0][0], a0, bA[0], bA[1]);
            mma16816(acc[0][1], a0, bA[2], bA[3]);
            mma16816(acc[0][2], a0, bB[0], bB[1]);
            mma16816(acc[0][3], a0, bB[2], bB[3]);
            mma16816(acc[1][0], a1, bA[0], bA[1]);
            mma16816(acc[1][1], a1, bA[2], bA[3]);
            mma16816(acc[1][2], a1, bB[0], bB[1]);
            mma16816(acc[1][3], a1, bB[2], bB[3]);
        }
        if (c + 1 < nk) {
            const int nb = buf ^ 1;
            *(uint4*)&smem[nb * BUFE + ar * PITCH + ak]           = av;
            *(uint4*)&smem[nb * BUFE + ASZ + br * PITCH + bk]     = bv0;
            *(uint4*)&smem[nb * BUFE + ASZ + br * PITCH + bk + 8] = bv1;
        }
        __syncthreads();
    }

#pragma unroll
    for (int i = 0; i < 2; i++) {
        int row = m0 + wm * 32 + i * 16 + (lane >> 2);
#pragma unroll
        for (int j = 0; j < 4; j++) {
            int col = n0 + wn * 32 + j * 8 + 2 * (lane & 3);
#pragma unroll
            for (int half = 0; half < 2; half++) {
                int r2 = row + half * 8;
                float v0 = acc[i][j][half * 2 + 0];
                float v1 = acc[i][j][half * 2 + 1];
                size_t oidx = (size_t)r2 * Nc + col;
                if (MODE == 0) {
                    // qkv bf16 with q pre-scaled by 0.125
                    float x0, x1;
                    if (col < C_) {
                        x0 = (v0 + b0[col]) * 0.125f;
                        x1 = (v1 + b0[col + 1]) * 0.125f;
                    } else if (col < 2 * C_) {
                        x0 = v0;
                        x1 = v1;
                    } else {
                        x0 = v0 + b1[col - 2 * C_];
                        x1 = v1 + b1[col + 1 - 2 * C_];
                    }
                    __nv_bfloat162* op = (__nv_bfloat162*)((__nv_bfloat16*)outv + oidx);
                    *op = __floats2bfloat162_rn(x0, x1);
                } else if (MODE == 1) {
                    float2* op = (float2*)((float*)outv + oidx);
                    float2 cur = *op;
                    cur.x += b1[col]     * (v0 + b0[col]);
                    cur.y += b1[col + 1] * (v1 + b0[col + 1]);
                    *op = cur;
                } else {
                    float x0 = v0 + b0[col];
                    float x1 = v1 + b0[col + 1];
                    x0 = x0 * normcdff(x0);
                    x1 = x1 * normcdff(x1);
                    __nv_bfloat162* op = (__nv_bfloat162*)((__nv_bfloat16*)outv + oidx);
                    *op = __floats2bfloat162_rn(x0, x1);
                }
            }
        }
    }
}

// ---------------- relative position bias ----------------
__global__ void relbias_kernel(const float* __restrict__ table, const int* __restrict__ ridx) {
    int i = blockIdx.x * 256 + threadIdx.x;
    if (i < NN_) {
        int id = ridx[i];
#pragma unroll
        for (int h = 0; h < H_; h++) g_bias[h * NN_ + i] = table[id * H_ + h];
    }
}

// ---------------- fused flash attention (HMMA), one block per (b,h) ----------------
// N padded to 208 (13 m16 tiles, 26 n8 tiles). 8 warps; warp w handles row tiles w, w+8.
#define QK_PITCH 72
#define VT_PITCH 216
#define SM_Q 0
#define SM_K (208 * QK_PITCH)                   // 14976 elems
#define SM_V (2 * 208 * QK_PITCH)               // 29952 elems
#define SM_TOT (2 * 208 * QK_PITCH + 64 * VT_PITCH)  // 43776 elems (87552 B)

__global__ __launch_bounds__(256) void attn_kernel(const __nv_bfloat16* __restrict__ qkv,
                                                   __nv_bfloat16* __restrict__ o) {
    extern __shared__ __nv_bfloat16 sm[];
    const int t = threadIdx.x;
    const int bh = blockIdx.x;
    const int b = bh / H_;
    const int h = bh % H_;

    // zero all smem (covers padding rows/cols)
    {
        uint4 zz = make_uint4(0u, 0u, 0u, 0u);
        for (int i = t; i < SM_TOT / 8; i += 256) *(uint4*)&sm[i * 8] = zz;
    }
    __syncthreads();

    // load Q, K rows and V transposed
    const __nv_bfloat16* base = qkv + (size_t)(b * N_) * (3 * C_) + h * D_;
    for (int i = t; i < N_ * 8; i += 256) {
        int row = i >> 3;
        int d8  = (i & 7) * 8;
        const __nv_bfloat16* rp = base + (size_t)row * (3 * C_);
        uint4 vq = *(const uint4*)(rp + d8);
        uint4 vk = *(const uint4*)(rp + C_ + d8);
        uint4 vv = *(const uint4*)(rp + 2 * C_ + d8);
        *(uint4*)&sm[SM_Q + row * QK_PITCH + d8] = vq;
        *(uint4*)&sm[SM_K + row * QK_PITCH + d8] = vk;
        __nv_bfloat16 tmp[8];
        *(uint4*)tmp = vv;
#pragma unroll
        for (int q = 0; q < 8; q++) sm[SM_V + (d8 + q) * VT_PITCH + row] = tmp[q];
    }
    __syncthreads();

    const int warp = t >> 5;
    const int lane = t & 31;
    const int g  = lane >> 3;
    const int rr = lane & 7;
    const unsigned usm = s2u(sm);
    const int arow = ((g & 1) << 3) + rr;   // A-frag row within tile
    const int acol = ((g >> 1) << 3);       // A-frag col offset
    const int brow = ((g >> 1) << 3) + rr;  // B-frag row within tile
    const int bcol = ((g & 1) << 3);        // B-frag col offset
    const int r0 = lane >> 2;
    const int cq = 2 * (lane & 3);
    const float* biasrow = g_bias + (size_t)h * NN_;

    for (int mt = warp; mt < 13; mt += 8) {
        const int R = mt * 16;
        // Q fragments for 4 k-steps
        unsigned aQ[4][4];
#pragma unroll
        for (int k = 0; k < 4; k++) {
            ldsm4(aQ[k][0], aQ[k][1], aQ[k][2], aQ[k][3],
                  usm + (unsigned)((SM_Q + (R + arow) * QK_PITCH + k * 16 + acol) * 2));
        }
        // S = Q @ K^T
        float S[26][4];
#pragma unroll
        for (int i = 0; i < 26; i++)
#pragma unroll
            for (int q = 0; q < 4; q++) S[i][q] = 0.f;
#pragma unroll
        for (int nt = 0; nt < 13; nt++) {
#pragma unroll
            for (int k = 0; k < 4; k++) {
                unsigned bk[4];
                ldsm4(bk[0], bk[1], bk[2], bk[3],
                      usm + (unsigned)((SM_K + (nt * 16 + brow) * QK_PITCH + k * 16 + bcol) * 2));
                mma16816(S[2 * nt],     aQ[k], bk[0], bk[1]);
                mma16816(S[2 * nt + 1], aQ[k], bk[2], bk[3]);
            }
        }
        // bias add + mask
        const int gr0 = R + r0;
        const int gr1 = gr0 + 8;
        float mx0 = -1e30f, mx1 = -1e30f;
#pragma unroll
        for (int nt = 0; nt < 26; nt++) {
            int c0 = nt * 8 + cq;
            int c1 = c0 + 1;
            float b00 = (gr0 < N_ && c0 < N_) ? __ldg(biasrow + gr0 * N_ + c0) : 0.f;
            float b01 = (gr0 < N_ && c1 < N_) ? __ldg(biasrow + gr0 * N_ + c1) : 0.f;
            float b10 = (gr1 < N_ && c0 < N_) ? __ldg(biasrow + gr1 * N_ + c0) : 0.f;
            float b11 = (gr1 < N_ && c1 < N_) ? __ldg(biasrow + gr1 * N_ + c1) : 0.f;
            S[nt][0] = (c0 < N_) ? S[nt][0] + b00 : -1e30f;
            S[nt][1] = (c1 < N_) ? S[nt][1] + b01 : -1e30f;
            S[nt][2] = (c0 < N_) ? S[nt][2] + b10 : -1e30f;
            S[nt][3] = (c1 < N_) ? S[nt][3] + b11 : -1e30f;
            mx0 = fmaxf(mx0, fmaxf(S[nt][0], S[nt][1]));
            mx1 = fmaxf(mx1, fmaxf(S[nt][2], S[nt][3]));
        }
        mx0 = fmaxf(mx0, __shfl_xor_sync(0xffffffffu, mx0, 1));
        mx0 = fmaxf(mx0, __shfl_xor_sync(0xffffffffu, mx0, 2));
        mx1 = fmaxf(mx1, __shfl_xor_sync(0xffffffffu, mx1, 1));
        mx1 = fmaxf(mx1, __shfl_xor_sync(0xffffffffu, mx1, 2));
        float sum0 = 0.f, sum1 = 0.f;
#pragma unroll
        for (int nt = 0; nt < 26; nt++) {
            S[nt][0] = __expf(S[nt][0] - mx0);
            S[nt][1] = __expf(S[nt][1] - mx0);
            S[nt][2] = __expf(S[nt][2] - mx1);
            S[nt][3] = __expf(S[nt][3] - mx1);
            sum0 += S[nt][0] + S[nt][1];
            sum1 += S[nt][2] + S[nt][3];
        }
        sum0 += __shfl_xor_sync(0xffffffffu, sum0, 1);
        sum0 += __shfl_xor_sync(0xffffffffu, sum0, 2);
        sum1 += __shfl_xor_sync(0xffffffffu, sum1, 1);
        sum1 += __shfl_xor_sync(0xffffffffu, sum1, 2);

        // O = P @ V  (P fragments from S registers)
        float O[8][4];
#pragma unroll
        for (int i = 0; i < 8; i++)
#pragma unroll
            for (int q = 0; q < 4; q++) O[i][q] = 0.f;
#pragma unroll
        for (int kt = 0; kt < 13; kt++) {
            unsigned aP[4];
            aP[0] = packbf(S[2 * kt][0],     S[2 * kt][1]);
            aP[1] = packbf(S[2 * kt][2],     S[2 * kt][3]);
            aP[2] = packbf(S[2 * kt + 1][0], S[2 * kt + 1][1]);
            aP[3] = packbf(S[2 * kt + 1][2], S[2 * kt + 1][3]);
#pragma unroll
            for (int p = 0; p < 4; p++) {
                unsigned bv[4];
                ldsm4(bv[0], bv[1], bv[2], bv[3],
                      usm + (unsigned)((SM_V + (p * 16 + brow) * VT_PITCH + kt * 16 + bcol) * 2));
                mma16816(O[2 * p],     aP, bv[0], bv[1]);
                mma16816(O[2 * p + 1], aP, bv[2], bv[3]);
            }
        }
        // normalize + write
        float inv0 = 1.f / sum0;
        float inv1 = 1.f / sum1;
#pragma unroll
        for (int dt = 0; dt < 8; dt++) {
            int col = h * D_ + dt * 8 + cq;
            if (gr0 < N_) {
                __nv_bfloat162* op = (__nv_bfloat162*)&o[(size_t)(b * N_ + gr0) * C_ + col];
                *op = __floats2bfloat162_rn(O[dt][0] * inv0, O[dt][1] * inv0);
            }
            if (gr1 < N_) {
                __nv_bfloat162* op = (__nv_bfloat162*)&o[(size_t)(b * N_ + gr1) * C_ + col];
                *op = __floats2bfloat162_rn(O[dt][2] * inv1, O[dt][3] * inv1);
            }
        }
    }
}

// ---------------- launch ----------------
extern "C" void kernel_launch(void* const* d_in, const int* in_sizes, int n_in,
                              void* d_out, int out_size) {
    const float* x      = (const float*)d_in[0];
    const float* qkv_w  = (const float*)d_in[1];
    const float* q_bias = (const float*)d_in[2];
    const float* v_bias = (const float*)d_in[3];
    const float* proj_w = (const float*)d_in[4];
    const float* proj_b = (const float*)d_in[5];
    const float* ln1_s  = (const float*)d_in[6];
    const float* ln1_b  = (const float*)d_in[7];
    const float* ln2_s  = (const float*)d_in[8];
    const float* ln2_b  = (const float*)d_in[9];
    const float* fc1_w  = (const float*)d_in[10];
    const float* fc1_b  = (const float*)d_in[11];
    const float* fc2_w  = (const float*)d_in[12];
    const float* fc2_b  = (const float*)d_in[13];
    const float* gamma1 = (const float*)d_in[14];
    const float* gamma2 = (const float*)d_in[15];
    const float* rtab   = (const float*)d_in[16];
    const int*   ridx   = (const int*)d_in[17];
    float* h = (float*)d_out;

    void* pz = 0;
    void* pqkv = 0;
    void* po = 0;
    void* pmlp = 0;
    void* pw = 0;
    cudaGetSymbolAddress(&pz, g_z);
    cudaGetSymbolAddress(&pqkv, g_qkvb);
    cudaGetSymbolAddress(&po, g_o);
    cudaGetSymbolAddress(&pmlp, g_mlp);
    cudaGetSymbolAddress(&pw, g_wbf);
    __nv_bfloat16* z    = (__nv_bfloat16*)pz;
    __nv_bfloat16* qkvb = (__nv_bfloat16*)pqkv;
    __nv_bfloat16* o    = (__nv_bfloat16*)po;
    __nv_bfloat16* mlp  = (__nv_bfloat16*)pmlp;
    __nv_bfloat16* wbf  = (__nv_bfloat16*)pw;

    const int attn_smem = SM_TOT * 2;  // 87552 B
    cudaFuncSetAttribute(attn_kernel, cudaFuncAttributeMaxDynamicSharedMemorySize, attn_smem);

    cudaMemcpyAsync(h, x, sizeof(float) * (size_t)M_ * C_, cudaMemcpyDeviceToDevice);
    relbias_kernel<<<(NN_ + 255) / 256, 256>>>(rtab, ridx);

    {
        int pq = 3 * C_ * C_;
        int pp = C_ * C_;
        int p1 = FF_ * C_;
        int p2 = C_ * FF_;
        int tq = DEPTH_ * pq / 4;
        int tp = DEPTH_ * pp / 4;
        int t1 = DEPTH_ * p1 / 4;
        int t2 = DEPTH_ * p2 / 4;
        cvtw_kernel<<<(tq + 255) / 256, 256>>>(qkv_w,  pq, W_QKV_OFF,  tq);
        cvtw_kernel<<<(tp + 255) / 256, 256>>>(proj_w, pp, W_PROJ_OFF, tp);
        cvtw_kernel<<<(t1 + 255) / 256, 256>>>(fc1_w,  p1, W_FC1_OFF,  t1);
        cvtw_kernel<<<(t2 + 255) / 256, 256>>>(fc2_w,  p2, W_FC2_OFF,  t2);
    }

    for (int l = 0; l < DEPTH_; l++) {
        const __nv_bfloat16* wl = wbf + (size_t)l * W_LSTRIDE;
        ln_kernel<<<M_, 256>>>(h, ln1_s + l * C_, ln1_b + l * C_, z);
        mma_gemm<0><<<dim3(3 * C_ / 128, M_ / 64), 256>>>(
            z, wl + W_QKV_OFF, (void*)qkvb, q_bias + l * C_, v_bias + l * C_, 3 * C_, C_);
        attn_kernel<<<B_ * H_, 256, attn_smem>>>(qkvb, o);
        mma_gemm<1><<<dim3(C_ / 128, M_ / 64), 256>>>(
            o, wl + W_PROJ_OFF, (void*)h, proj_b + l * C_, gamma1 + l * C_, C_, C_);
        ln_kernel<<<M_, 256>>>(h, ln2_s + l * C_, ln2_b + l * C_, z);
        mma_gemm<2><<<dim3(FF_ / 128, M_ / 64), 256>>>(
            z, wl + W_FC1_OFF, (void*)mlp, fc1_b + l * FF_, (const float*)0, FF_, C_);
        mma_gemm<1><<<dim3(C_ / 128, M_ / 64), 256>>>(
            mlp, wl + W_FC2_OFF, (void*)h, fc2_b + l * C_, gamma2 + l * C_, C_, FF_);
    }
}

// round 6
// speedup vs baseline: 7.3648x; 1.2305x over previous
#include <cuda_runtime.h>
#include <cuda_bf16.h>
#include <cstdint>
#include <cstddef>
#include <math.h>

#define B_     64
#define N_     197
#define C_     768
#define H_     12
#define D_     64
#define FF_    3072
#define DEPTH_ 12
#define M_     (B_ * N_)
#define NN_    (N_ * N_)

#define W_QKV_OFF  0
#define W_PROJ_OFF (3 * C_ * C_)
#define W_FC1_OFF  (W_PROJ_OFF + C_ * C_)
#define W_FC2_OFF  (W_FC1_OFF + FF_ * C_)
#define W_LSTRIDE  (W_FC2_OFF + C_ * FF_)

// ---------------- scratch (device globals) ----------------
__device__ __nv_bfloat16 g_z[M_ * C_];
__device__ __nv_bfloat16 g_qkvb[(size_t)M_ * 3 * C_];
__device__ __nv_bfloat16 g_o[M_ * C_];
__device__ __nv_bfloat16 g_mlp[(size_t)M_ * FF_];
__device__ float         g_bias[H_ * NN_];
__device__ __nv_bfloat16 g_wbf[(size_t)DEPTH_ * W_LSTRIDE];

// ---------------- helpers ----------------
__device__ __forceinline__ float warp_sum(float v) {
#pragma unroll
    for (int o = 16; o > 0; o >>= 1) v += __shfl_xor_sync(0xffffffffu, v, o);
    return v;
}

__device__ __forceinline__ unsigned s2u(const void* p) {
    return (unsigned)__cvta_generic_to_shared(p);
}

__device__ __forceinline__ void ldsm4(unsigned& r0, unsigned& r1, unsigned& r2, unsigned& r3,
                                      unsigned addr) {
    asm volatile("ldmatrix.sync.aligned.m8n8.x4.shared.b16 {%0,%1,%2,%3}, [%4];"
                 : "=r"(r0), "=r"(r1), "=r"(r2), "=r"(r3)
                 : "r"(addr));
}

__device__ __forceinline__ void mma16816(float* c, const unsigned* a, unsigned b0, unsigned b1) {
    asm volatile(
        "mma.sync.aligned.m16n8k16.row.col.f32.bf16.bf16.f32 "
        "{%0,%1,%2,%3}, {%4,%5,%6,%7}, {%8,%9}, {%0,%1,%2,%3};"
        : "+f"(c[0]), "+f"(c[1]), "+f"(c[2]), "+f"(c[3])
        : "r"(a[0]), "r"(a[1]), "r"(a[2]), "r"(a[3]), "r"(b0), "r"(b1));
}

__device__ __forceinline__ unsigned packbf(float x, float y) {
    __nv_bfloat162 t = __floats2bfloat162_rn(x, y);
    return *(unsigned*)&t;
}

__device__ __forceinline__ void cpa16(unsigned saddr, const void* g) {
    asm volatile("cp.async.ca.shared.global [%0], [%1], 16;" :: "r"(saddr), "l"(g));
}

// ---------------- weight fp32 -> bf16 ----------------
__global__ void cvtw_kernel(const float* __restrict__ src, int per_layer,
                            int toff, int total4) {
    int i = blockIdx.x * 256 + threadIdx.x;
    if (i >= total4) return;
    int e = i * 4;
    int l = e / per_layer;
    int w = e % per_layer;
    float4 v = *(const float4*)(src + e);
    __nv_bfloat16* d = g_wbf + (size_t)l * W_LSTRIDE + toff + w;
    d[0] = __float2bfloat16(v.x);
    d[1] = __float2bfloat16(v.y);
    d[2] = __float2bfloat16(v.z);
    d[3] = __float2bfloat16(v.w);
}

// ---------------- LayerNorm -> bf16 ----------------
__global__ __launch_bounds__(256) void ln_kernel(const float* __restrict__ x,
                                                 const float* __restrict__ s,
                                                 const float* __restrict__ bsh,
                                                 __nv_bfloat16* __restrict__ z) {
    int row = blockIdx.x;
    const float* xr = x + (size_t)row * C_;
    float v0 = xr[threadIdx.x];
    float v1 = xr[threadIdx.x + 256];
    float v2 = xr[threadIdx.x + 512];
    float sum = v0 + v1 + v2;
    float sq  = v0 * v0 + v1 * v1 + v2 * v2;
    sum = warp_sum(sum);
    sq  = warp_sum(sq);
    __shared__ float sh1[8];
    __shared__ float sh2[8];
    int w = threadIdx.x >> 5;
    int lane = threadIdx.x & 31;
    if (lane == 0) { sh1[w] = sum; sh2[w] = sq; }
    __syncthreads();
    if (w == 0) {
        float a  = (lane < 8) ? sh1[lane] : 0.f;
        float b2 = (lane < 8) ? sh2[lane] : 0.f;
        a  = warp_sum(a);
        b2 = warp_sum(b2);
        if (lane == 0) { sh1[0] = a; sh2[0] = b2; }
    }
    __syncthreads();
    float mean = sh1[0] * (1.f / C_);
    float var  = sh2[0] * (1.f / C_) - mean * mean;
    float r    = rsqrtf(var + 1e-5f);
    int c0 = threadIdx.x;
    z[(size_t)row * C_ + c0]       = __float2bfloat16((v0 - mean) * r * s[c0]       + bsh[c0]);
    z[(size_t)row * C_ + c0 + 256] = __float2bfloat16((v1 - mean) * r * s[c0 + 256] + bsh[c0 + 256]);
    z[(size_t)row * C_ + c0 + 512] = __float2bfloat16((v2 - mean) * r * s[c0 + 512] + bsh[c0 + 512]);
}

// ---------------- bf16 HMMA GEMM, cp.async 3-stage pipeline ----------------
// out[M,Nc] = A[M,K] @ W[Nc,K]^T + epilogue.
// BM=64 BN=256 BK=32, 256 threads (8 warps 2x4), warp tile 32x64.
// MODE 0: bf16 out = (acc + q_bias)*0.125 | acc | acc + v_bias
// MODE 1: fp32 out += b1[col]*(acc + b0[col])
// MODE 2: bf16 out = gelu(acc + b0[col])
#define GP     40
#define G_ASZ  (64 * GP)               // 2560 elems
#define G_BSZ  (256 * GP)              // 10240 elems
#define G_STG  (G_ASZ + G_BSZ)         // 12800 elems (25600 B)

template <int MODE>
__global__ __launch_bounds__(256) void mma_gemm(const __nv_bfloat16* __restrict__ A,
                                                const __nv_bfloat16* __restrict__ W,
                                                void* __restrict__ outv,
                                                const float* __restrict__ b0,
                                                const float* __restrict__ b1,
                                                int Nc, int K) {
    extern __shared__ __nv_bfloat16 smem[];   // 3 * G_STG elems
    const int t    = threadIdx.x;
    const int warp = t >> 5;
    const int lane = t & 31;
    const int wm = warp >> 2;
    const int wn = warp & 3;
    const int m0 = blockIdx.y * 64;
    const int n0 = blockIdx.x * 256;

    // global load mapping: thread t -> A row t>>2, chunk t&3 (8 bf16)
    //                      B rows (t>>2)+i*64, chunk t&3, i=0..3
    const int lr = t >> 2;
    const int lc = (t & 3) * 8;
    const __nv_bfloat16* Ag = A + (size_t)(m0 + lr) * K + lc;
    const __nv_bfloat16* Wg = W + (size_t)(n0 + lr) * K + lc;
    const unsigned usm = s2u(smem);
    const unsigned sA = (unsigned)((lr * GP + lc) * 2);
    const unsigned sB = (unsigned)((G_ASZ + lr * GP + lc) * 2);

    // ldmatrix fragment offsets
    const int g  = lane >> 3;
    const int rr = lane & 7;
    const unsigned aoff = (unsigned)(((wm * 32 + ((g & 1) << 3) + rr) * GP + ((g >> 1) << 3)) * 2);
    const unsigned boff = (unsigned)((G_ASZ + (wn * 64 + ((g >> 1) << 3) + rr) * GP + ((g & 1) << 3)) * 2);

    float acc[2][8][4];
#pragma unroll
    for (int i = 0; i < 2; i++)
#pragma unroll
        for (int j = 0; j < 8; j++)
#pragma unroll
            for (int q = 0; q < 4; q++) acc[i][j][q] = 0.f;

    const int nk = K / 32;
    const unsigned STB = (unsigned)(G_STG * 2);

    // prologue: stages 0,1
#pragma unroll
    for (int s = 0; s < 2; s++) {
        unsigned base = usm + s * STB;
        cpa16(base + sA, Ag + s * 32);
#pragma unroll
        for (int i = 0; i < 4; i++)
            cpa16(base + sB + (unsigned)(i * 64 * GP * 2), Wg + (size_t)i * 64 * K + s * 32);
        asm volatile("cp.async.commit_group;");
    }

    for (int c = 0; c < nk; c++) {
        asm volatile("cp.async.wait_group 1;");
        __syncthreads();
        const unsigned base = usm + (unsigned)(c % 3) * STB;
#pragma unroll
        for (int ks = 0; ks < 2; ks++) {
            unsigned af[2][4];
            unsigned bf[4][4];
#pragma unroll
            for (int i = 0; i < 2; i++)
                ldsm4(af[i][0], af[i][1], af[i][2], af[i][3],
                      base + aoff + (unsigned)(i * 16 * GP * 2 + ks * 32));
#pragma unroll
            for (int j = 0; j < 4; j++)
                ldsm4(bf[j][0], bf[j][1], bf[j][2], bf[j][3],
                      base + boff + (unsigned)(j * 16 * GP * 2 + ks * 32));
#pragma unroll
            for (int i = 0; i < 2; i++) {
#pragma unroll
                for (int j = 0; j < 4; j++) {
                    mma16816(acc[i][2 * j],     af[i], bf[j][0], bf[j][1]);
                    mma16816(acc[i][2 * j + 1], af[i], bf[j][2], bf[j][3]);
                }
            }
        }
        if (c + 2 < nk) {
            const unsigned nbase = usm + (unsigned)((c + 2) % 3) * STB;
            cpa16(nbase + sA, Ag + (c + 2) * 32);
#pragma unroll
            for (int i = 0; i < 4; i++)
                cpa16(nbase + sB + (unsigned)(i * 64 * GP * 2),
                      Wg + (size_t)i * 64 * K + (c + 2) * 32);
        }
        asm volatile("cp.async.commit_group;");
    }

    // epilogue
#pragma unroll
    for (int i = 0; i < 2; i++) {
        int row = m0 + wm * 32 + i * 16 + (lane >> 2);
#pragma unroll
        for (int j = 0; j < 8; j++) {
            int col = n0 + wn * 64 + j * 8 + 2 * (lane & 3);
#pragma unroll
            for (int half = 0; half < 2; half++) {
                int r2 = row + half * 8;
                float v0 = acc[i][j][half * 2 + 0];
                float v1 = acc[i][j][half * 2 + 1];
                size_t oidx = (size_t)r2 * Nc + col;
                if (MODE == 0) {
                    float x0, x1;
                    if (col < C_) {
                        x0 = (v0 + b0[col]) * 0.125f;
                        x1 = (v1 + b0[col + 1]) * 0.125f;
                    } else if (col < 2 * C_) {
                        x0 = v0;
                        x1 = v1;
                    } else {
                        x0 = v0 + b1[col - 2 * C_];
                        x1 = v1 + b1[col + 1 - 2 * C_];
                    }
                    __nv_bfloat162* op = (__nv_bfloat162*)((__nv_bfloat16*)outv + oidx);
                    *op = __floats2bfloat162_rn(x0, x1);
                } else if (MODE == 1) {
                    float2* op = (float2*)((float*)outv + oidx);
                    float2 cur = *op;
                    cur.x += b1[col]     * (v0 + b0[col]);
                    cur.y += b1[col + 1] * (v1 + b0[col + 1]);
                    *op = cur;
                } else {
                    float x0 = v0 + b0[col];
                    float x1 = v1 + b0[col + 1];
                    x0 = x0 * normcdff(x0);
                    x1 = x1 * normcdff(x1);
                    __nv_bfloat162* op = (__nv_bfloat162*)((__nv_bfloat16*)outv + oidx);
                    *op = __floats2bfloat162_rn(x0, x1);
                }
            }
        }
    }
}

// ---------------- relative position bias ----------------
__global__ void relbias_kernel(const float* __restrict__ table, const int* __restrict__ ridx) {
    int i = blockIdx.x * 256 + threadIdx.x;
    if (i < NN_) {
        int id = ridx[i];
#pragma unroll
        for (int h = 0; h < H_; h++) g_bias[h * NN_ + i] = table[id * H_ + h];
    }
}

// ---------------- fused flash attention (HMMA), one block per (b,h) ----------------
#define QK_PITCH 72
#define VT_PITCH 216
#define SM_Q 0
#define SM_K (208 * QK_PITCH)
#define SM_V (2 * 208 * QK_PITCH)
#define SM_TOT (2 * 208 * QK_PITCH + 64 * VT_PITCH)

__global__ __launch_bounds__(256) void attn_kernel(const __nv_bfloat16* __restrict__ qkv,
                                                   __nv_bfloat16* __restrict__ o) {
    extern __shared__ __nv_bfloat16 sm[];
    const int t = threadIdx.x;
    const int bh = blockIdx.x;
    const int b = bh / H_;
    const int h = bh % H_;

    {
        uint4 zz = make_uint4(0u, 0u, 0u, 0u);
        for (int i = t; i < SM_TOT / 8; i += 256) *(uint4*)&sm[i * 8] = zz;
    }
    __syncthreads();

    const __nv_bfloat16* base = qkv + (size_t)(b * N_) * (3 * C_) + h * D_;
    for (int i = t; i < N_ * 8; i += 256) {
        int row = i >> 3;
        int d8  = (i & 7) * 8;
        const __nv_bfloat16* rp = base + (size_t)row * (3 * C_);
        uint4 vq = *(const uint4*)(rp + d8);
        uint4 vk = *(const uint4*)(rp + C_ + d8);
        uint4 vv = *(const uint4*)(rp + 2 * C_ + d8);
        *(uint4*)&sm[SM_Q + row * QK_PITCH + d8] = vq;
        *(uint4*)&sm[SM_K + row * QK_PITCH + d8] = vk;
        __nv_bfloat16 tmp[8];
        *(uint4*)tmp = vv;
#pragma unroll
        for (int q = 0; q < 8; q++) sm[SM_V + (d8 + q) * VT_PITCH + row] = tmp[q];
    }
    __syncthreads();

    const int warp = t >> 5;
    const int lane = t & 31;
    const int g  = lane >> 3;
    const int rr = lane & 7;
    const unsigned usm = s2u(sm);
    const int arow = ((g & 1) << 3) + rr;
    const int acol = ((g >> 1) << 3);
    const int brow = ((g >> 1) << 3) + rr;
    const int bcol = ((g & 1) << 3);
    const int r0 = lane >> 2;
    const int cq = 2 * (lane & 3);
    const float* biasrow = g_bias + (size_t)h * NN_;

    for (int mt = warp; mt < 13; mt += 8) {
        const int R = mt * 16;
        unsigned aQ[4][4];
#pragma unroll
        for (int k = 0; k < 4; k++) {
            ldsm4(aQ[k][0], aQ[k][1], aQ[k][2], aQ[k][3],
                  usm + (unsigned)((SM_Q + (R + arow) * QK_PITCH + k * 16 + acol) * 2));
        }
        float S[26][4];
#pragma unroll
        for (int i = 0; i < 26; i++)
#pragma unroll
            for (int q = 0; q < 4; q++) S[i][q] = 0.f;
#pragma unroll
        for (int nt = 0; nt < 13; nt++) {
#pragma unroll
            for (int k = 0; k < 4; k++) {
                unsigned bk[4];
                ldsm4(bk[0], bk[1], bk[2], bk[3],
                      usm + (unsigned)((SM_K + (nt * 16 + brow) * QK_PITCH + k * 16 + bcol) * 2));
                mma16816(S[2 * nt],     aQ[k], bk[0], bk[1]);
                mma16816(S[2 * nt + 1], aQ[k], bk[2], bk[3]);
            }
        }
        const int gr0 = R + r0;
        const int gr1 = gr0 + 8;
        float mx0 = -1e30f, mx1 = -1e30f;
#pragma unroll
        for (int nt = 0; nt < 26; nt++) {
            int c0 = nt * 8 + cq;
            int c1 = c0 + 1;
            float b00 = (gr0 < N_ && c0 < N_) ? __ldg(biasrow + gr0 * N_ + c0) : 0.f;
            float b01 = (gr0 < N_ && c1 < N_) ? __ldg(biasrow + gr0 * N_ + c1) : 0.f;
            float b10 = (gr1 < N_ && c0 < N_) ? __ldg(biasrow + gr1 * N_ + c0) : 0.f;
            float b11 = (gr1 < N_ && c1 < N_) ? __ldg(biasrow + gr1 * N_ + c1) : 0.f;
            S[nt][0] = (c0 < N_) ? S[nt][0] + b00 : -1e30f;
            S[nt][1] = (c1 < N_) ? S[nt][1] + b01 : -1e30f;
            S[nt][2] = (c0 < N_) ? S[nt][2] + b10 : -1e30f;
            S[nt][3] = (c1 < N_) ? S[nt][3] + b11 : -1e30f;
            mx0 = fmaxf(mx0, fmaxf(S[nt][0], S[nt][1]));
            mx1 = fmaxf(mx1, fmaxf(S[nt][2], S[nt][3]));
        }
        mx0 = fmaxf(mx0, __shfl_xor_sync(0xffffffffu, mx0, 1));
        mx0 = fmaxf(mx0, __shfl_xor_sync(0xffffffffu, mx0, 2));
        mx1 = fmaxf(mx1, __shfl_xor_sync(0xffffffffu, mx1, 1));
        mx1 = fmaxf(mx1, __shfl_xor_sync(0xffffffffu, mx1, 2));
        float sum0 = 0.f, sum1 = 0.f;
#pragma unroll
        for (int nt = 0; nt < 26; nt++) {
            S[nt][0] = __expf(S[nt][0] - mx0);
            S[nt][1] = __expf(S[nt][1] - mx0);
            S[nt][2] = __expf(S[nt][2] - mx1);
            S[nt][3] = __expf(S[nt][3] - mx1);
            sum0 += S[nt][0] + S[nt][1];
            sum1 += S[nt][2] + S[nt][3];
        }
        sum0 += __shfl_xor_sync(0xffffffffu, sum0, 1);
        sum0 += __shfl_xor_sync(0xffffffffu, sum0, 2);
        sum1 += __shfl_xor_sync(0xffffffffu, sum1, 1);
        sum1 += __shfl_xor_sync(0xffffffffu, sum1, 2);

        float O[8][4];
#pragma unroll
        for (int i = 0; i < 8; i++)
#pragma unroll
            for (int q = 0; q < 4; q++) O[i][q] = 0.f;
#pragma unroll
        for (int kt = 0; kt < 13; kt++) {
            unsigned aP[4];
            aP[0] = packbf(S[2 * kt][0],     S[2 * kt][1]);
            aP[1] = packbf(S[2 * kt][2],     S[2 * kt][3]);
            aP[2] = packbf(S[2 * kt + 1][0], S[2 * kt + 1][1]);
            aP[3] = packbf(S[2 * kt + 1][2], S[2 * kt + 1][3]);
#pragma unroll
            for (int p = 0; p < 4; p++) {
                unsigned bv[4];
                ldsm4(bv[0], bv[1], bv[2], bv[3],
                      usm + (unsigned)((SM_V + (p * 16 + brow) * VT_PITCH + kt * 16 + bcol) * 2));
                mma16816(O[2 * p],     aP, bv[0], bv[1]);
                mma16816(O[2 * p + 1], aP, bv[2], bv[3]);
            }
        }
        float inv0 = 1.f / sum0;
        float inv1 = 1.f / sum1;
#pragma unroll
        for (int dt = 0; dt < 8; dt++) {
            int col = h * D_ + dt * 8 + cq;
            if (gr0 < N_) {
                __nv_bfloat162* op = (__nv_bfloat162*)&o[(size_t)(b * N_ + gr0) * C_ + col];
                *op = __floats2bfloat162_rn(O[dt][0] * inv0, O[dt][1] * inv0);
            }
            if (gr1 < N_) {
                __nv_bfloat162* op = (__nv_bfloat162*)&o[(size_t)(b * N_ + gr1) * C_ + col];
                *op = __floats2bfloat162_rn(O[dt][2] * inv1, O[dt][3] * inv1);
            }
        }
    }
}

// ---------------- launch ----------------
extern "C" void kernel_launch(void* const* d_in, const int* in_sizes, int n_in,
                              void* d_out, int out_size) {
    const float* x      = (const float*)d_in[0];
    const float* qkv_w  = (const float*)d_in[1];
    const float* q_bias = (const float*)d_in[2];
    const float* v_bias = (const float*)d_in[3];
    const float* proj_w = (const float*)d_in[4];
    const float* proj_b = (const float*)d_in[5];
    const float* ln1_s  = (const float*)d_in[6];
    const float* ln1_b  = (const float*)d_in[7];
    const float* ln2_s  = (const float*)d_in[8];
    const float* ln2_b  = (const float*)d_in[9];
    const float* fc1_w  = (const float*)d_in[10];
    const float* fc1_b  = (const float*)d_in[11];
    const float* fc2_w  = (const float*)d_in[12];
    const float* fc2_b  = (const float*)d_in[13];
    const float* gamma1 = (const float*)d_in[14];
    const float* gamma2 = (const float*)d_in[15];
    const float* rtab   = (const float*)d_in[16];
    const int*   ridx   = (const int*)d_in[17];
    float* h = (float*)d_out;

    void* pz = 0;
    void* pqkv = 0;
    void* po = 0;
    void* pmlp = 0;
    void* pw = 0;
    cudaGetSymbolAddress(&pz, g_z);
    cudaGetSymbolAddress(&pqkv, g_qkvb);
    cudaGetSymbolAddress(&po, g_o);
    cudaGetSymbolAddress(&pmlp, g_mlp);
    cudaGetSymbolAddress(&pw, g_wbf);
    __nv_bfloat16* z    = (__nv_bfloat16*)pz;
    __nv_bfloat16* qkvb = (__nv_bfloat16*)pqkv;
    __nv_bfloat16* o    = (__nv_bfloat16*)po;
    __nv_bfloat16* mlp  = (__nv_bfloat16*)pmlp;
    __nv_bfloat16* wbf  = (__nv_bfloat16*)pw;

    const int attn_smem = SM_TOT * 2;
    const int gemm_smem = 3 * G_STG * 2;  // 76800 B
    cudaFuncSetAttribute(attn_kernel, cudaFuncAttributeMaxDynamicSharedMemorySize, attn_smem);
    cudaFuncSetAttribute(mma_gemm<0>, cudaFuncAttributeMaxDynamicSharedMemorySize, gemm_smem);
    cudaFuncSetAttribute(mma_gemm<1>, cudaFuncAttributeMaxDynamicSharedMemorySize, gemm_smem);
    cudaFuncSetAttribute(mma_gemm<2>, cudaFuncAttributeMaxDynamicSharedMemorySize, gemm_smem);

    cudaMemcpyAsync(h, x, sizeof(float) * (size_t)M_ * C_, cudaMemcpyDeviceToDevice);
    relbias_kernel<<<(NN_ + 255) / 256, 256>>>(rtab, ridx);

    {
        int pq = 3 * C_ * C_;
        int pp = C_ * C_;
        int p1 = FF_ * C_;
        int p2 = C_ * FF_;
        int tq = DEPTH_ * pq / 4;
        int tp = DEPTH_ * pp / 4;
        int t1 = DEPTH_ * p1 / 4;
        int t2 = DEPTH_ * p2 / 4;
        cvtw_kernel<<<(tq + 255) / 256, 256>>>(qkv_w,  pq, W_QKV_OFF,  tq);
        cvtw_kernel<<<(tp + 255) / 256, 256>>>(proj_w, pp, W_PROJ_OFF, tp);
        cvtw_kernel<<<(t1 + 255) / 256, 256>>>(fc1_w,  p1, W_FC1_OFF,  t1);
        cvtw_kernel<<<(t2 + 255) / 256, 256>>>(fc2_w,  p2, W_FC2_OFF,  t2);
    }

    for (int l = 0; l < DEPTH_; l++) {
        const __nv_bfloat16* wl = wbf + (size_t)l * W_LSTRIDE;
        ln_kernel<<<M_, 256>>>(h, ln1_s + l * C_, ln1_b + l * C_, z);
        mma_gemm<0><<<dim3(3 * C_ / 256, M_ / 64), 256, gemm_smem>>>(
            z, wl + W_QKV_OFF, (void*)qkvb, q_bias + l * C_, v_bias + l * C_, 3 * C_, C_);
        attn_kernel<<<B_ * H_, 256, attn_smem>>>(qkvb, o);
        mma_gemm<1><<<dim3(C_ / 256, M_ / 64), 256, gemm_smem>>>(
            o, wl + W_PROJ_OFF, (void*)h, proj_b + l * C_, gamma1 + l * C_, C_, C_);
        ln_kernel<<<M_, 256>>>(h, ln2_s + l * C_, ln2_b + l * C_, z);
        mma_gemm<2><<<dim3(FF_ / 256, M_ / 64), 256, gemm_smem>>>(
            z, wl + W_FC1_OFF, (void*)mlp, fc1_b + l * FF_, (const float*)0, FF_, C_);
        mma_gemm<1><<<dim3(C_ / 256, M_ / 64), 256, gemm_smem>>>(
            mlp, wl + W_FC2_OFF, (void*)h, fc2_b + l * C_, gamma2 + l * C_, C_, FF_);
    }
}

// round 8
// speedup vs baseline: 9.4626x; 1.2848x over previous
#include <cuda_runtime.h>
#include <cuda_bf16.h>
#include <cuda_fp8.h>
#include <cstdint>
#include <cstddef>
#include <math.h>

#define B_     64
#define N_     197
#define C_     768
#define H_     12
#define D_     64
#define FF_    3072
#define DEPTH_ 12
#define M_     (B_ * N_)
#define NN_    (N_ * N_)
#define M_PAD  12800

#define W_QKV_OFF  0
#define W_PROJ_OFF (3 * C_ * C_)
#define W_FC1_OFF  (W_PROJ_OFF + C_ * C_)
#define W_FC2_OFF  (W_FC1_OFF + FF_ * C_)
#define W_LSTRIDE  (W_FC2_OFF + C_ * FF_)

#define WSCALE   64.0f
#define INV64    0.015625f

// ---------------- scratch (device globals; zero-initialized) ----------------
__device__ unsigned char g_z[(size_t)M_PAD * C_];          // LN out (e4m3)
__device__ __nv_bfloat16 g_qkvb[(size_t)M_PAD * 3 * C_];   // qkv (bf16, q pre-scaled)
__device__ unsigned char g_o[(size_t)M_PAD * C_];          // attn out (e4m3)
__device__ unsigned char g_mlp[(size_t)M_PAD * FF_];       // MLP hidden (e4m3)
__device__ float         g_bias[H_ * NN_];
__device__ unsigned char g_wbf[(size_t)DEPTH_ * W_LSTRIDE];// weights (e4m3, x64)

// ---------------- helpers ----------------
__device__ __forceinline__ float warp_sum(float v) {
#pragma unroll
    for (int o = 16; o > 0; o >>= 1) v += __shfl_xor_sync(0xffffffffu, v, o);
    return v;
}
__device__ __forceinline__ unsigned s2u(const void* p) {
    return (unsigned)__cvta_generic_to_shared(p);
}
__device__ __forceinline__ void ldsm4(unsigned& r0, unsigned& r1, unsigned& r2, unsigned& r3,
                                      unsigned addr) {
    asm volatile("ldmatrix.sync.aligned.m8n8.x4.shared.b16 {%0,%1,%2,%3}, [%4];"
                 : "=r"(r0), "=r"(r1), "=r"(r2), "=r"(r3)
                 : "r"(addr));
}
__device__ __forceinline__ void mma16816(float* c, const unsigned* a, unsigned b0, unsigned b1) {
    asm volatile(
        "mma.sync.aligned.m16n8k16.row.col.f32.bf16.bf16.f32 "
        "{%0,%1,%2,%3}, {%4,%5,%6,%7}, {%8,%9}, {%0,%1,%2,%3};"
        : "+f"(c[0]), "+f"(c[1]), "+f"(c[2]), "+f"(c[3])
        : "r"(a[0]), "r"(a[1]), "r"(a[2]), "r"(a[3]), "r"(b0), "r"(b1));
}
__device__ __forceinline__ void mma16832f8(float* c, const unsigned* a, unsigned b0, unsigned b1) {
    asm volatile(
        "mma.sync.aligned.m16n8k32.row.col.f32.e4m3.e4m3.f32 "
        "{%0,%1,%2,%3}, {%4,%5,%6,%7}, {%8,%9}, {%0,%1,%2,%3};"
        : "+f"(c[0]), "+f"(c[1]), "+f"(c[2]), "+f"(c[3])
        : "r"(a[0]), "r"(a[1]), "r"(a[2]), "r"(a[3]), "r"(b0), "r"(b1));
}
__device__ __forceinline__ unsigned packbf(float x, float y) {
    __nv_bfloat162 t = __floats2bfloat162_rn(x, y);
    return *(unsigned*)&t;
}
__device__ __forceinline__ void cpa16(unsigned saddr, const void* g) {
    asm volatile("cp.async.ca.shared.global [%0], [%1], 16;" :: "r"(saddr), "l"(g));
}
__device__ __forceinline__ unsigned char f2e4m3(float x) {
    return (unsigned char)__nv_cvt_float_to_fp8(x, __NV_SATFINITE, __NV_E4M3);
}

// ---------------- weight fp32 -> e4m3 (x64) ----------------
__global__ void cvtw_kernel(const float* __restrict__ src, int per_layer,
                            int toff, int total4) {
    int i = blockIdx.x * 256 + threadIdx.x;
    if (i >= total4) return;
    int e = i * 4;
    int l = e / per_layer;
    int w = e % per_layer;
    float4 v = *(const float4*)(src + e);
    unsigned char* d = g_wbf + (size_t)l * W_LSTRIDE + toff + w;
    d[0] = f2e4m3(v.x * WSCALE);
    d[1] = f2e4m3(v.y * WSCALE);
    d[2] = f2e4m3(v.z * WSCALE);
    d[3] = f2e4m3(v.w * WSCALE);
}

// ---------------- LayerNorm -> e4m3 ----------------
__global__ __launch_bounds__(256) void ln_kernel(const float* __restrict__ x,
                                                 const float* __restrict__ s,
                                                 const float* __restrict__ bsh,
                                                 unsigned char* __restrict__ z) {
    int row = blockIdx.x;
    const float* xr = x + (size_t)row * C_;
    float v0 = xr[threadIdx.x];
    float v1 = xr[threadIdx.x + 256];
    float v2 = xr[threadIdx.x + 512];
    float sum = v0 + v1 + v2;
    float sq  = v0 * v0 + v1 * v1 + v2 * v2;
    sum = warp_sum(sum);
    sq  = warp_sum(sq);
    __shared__ float sh1[8];
    __shared__ float sh2[8];
    int w = threadIdx.x >> 5;
    int lane = threadIdx.x & 31;
    if (lane == 0) { sh1[w] = sum; sh2[w] = sq; }
    __syncthreads();
    if (w == 0) {
        float a  = (lane < 8) ? sh1[lane] : 0.f;
        float b2 = (lane < 8) ? sh2[lane] : 0.f;
        a  = warp_sum(a);
        b2 = warp_sum(b2);
        if (lane == 0) { sh1[0] = a; sh2[0] = b2; }
    }
    __syncthreads();
    float mean = sh1[0] * (1.f / C_);
    float var  = sh2[0] * (1.f / C_) - mean * mean;
    float r    = rsqrtf(var + 1e-5f);
    int c0 = threadIdx.x;
    z[(size_t)row * C_ + c0]       = f2e4m3((v0 - mean) * r * s[c0]       + bsh[c0]);
    z[(size_t)row * C_ + c0 + 256] = f2e4m3((v1 - mean) * r * s[c0 + 256] + bsh[c0 + 256]);
    z[(size_t)row * C_ + c0 + 512] = f2e4m3((v2 - mean) * r * s[c0 + 512] + bsh[c0 + 512]);
}

// ---------------- FP8 mma.sync GEMM ----------------
// out[M,Nc] = A[M,K](e4m3) @ (64*W)[Nc,K](e4m3)^T / 64 + epilogue
// BM=128 BN=256 BK=64(bytes), 512 threads (16 warps 4x4), warp tile 32x64,
// 3-stage cp.async pipeline, smem pitch 80B (conflict-free ldmatrix).
// MODE 0: bf16 out = (acc/64 + q_bias)*0.125 | acc/64 | acc/64 + v_bias
// MODE 1: fp32 out += b1[col]*(acc/64 + b0[col])
// MODE 2: e4m3 out = gelu(acc/64 + b0[col])
#define P8      80
#define STG8_A  (128 * P8)              // 10240 B
#define STG8    (STG8_A + 256 * P8)     // 30720 B
#define SMEM8   (3 * STG8)              // 92160 B

__device__ __forceinline__ void fp8_load_chunk(unsigned base,
                                               const unsigned char* A,
                                               const unsigned char* W,
                                               int m0, int n0, int K, int c, int t) {
    const int cc = c * 64;
    {
        int row = t >> 2;
        int seg = (t & 3) * 16;
        cpa16(base + (unsigned)(row * P8 + seg), A + (size_t)(m0 + row) * K + cc + seg);
    }
#pragma unroll
    for (int i = 0; i < 2; i++) {
        int idx = i * 512 + t;
        int row = idx >> 2;
        int seg = (idx & 3) * 16;
        cpa16(base + (unsigned)(STG8_A + row * P8 + seg),
              W + (size_t)(n0 + row) * K + cc + seg);
    }
}

template <int MODE>
__global__ __launch_bounds__(512) void fp8_gemm(const unsigned char* __restrict__ A,
                                                const unsigned char* __restrict__ W,
                                                void* __restrict__ outv,
                                                const float* __restrict__ b0,
                                                const float* __restrict__ b1,
                                                int Nc, int K) {
    extern __shared__ unsigned char sm8[];
    const int t = threadIdx.x;
    const int warp = t >> 5;
    const int lane = t & 31;
    const int wm = warp >> 2;
    const int wn = warp & 3;
    const int m0 = blockIdx.y * 128;
    const int n0 = blockIdx.x * 256;
    const unsigned usm = s2u(sm8);

    const int g  = lane >> 3;
    const int rr = lane & 7;
    const unsigned aoff = (unsigned)((wm * 32 + ((g & 1) << 3) + rr) * P8 + (g >> 1) * 16);
    const unsigned boff = (unsigned)(STG8_A + (wn * 64 + ((g >> 1) << 3) + rr) * P8 + (g & 1) * 16);

    float acc[2][8][4];
#pragma unroll
    for (int i = 0; i < 2; i++)
#pragma unroll
        for (int j = 0; j < 8; j++)
#pragma unroll
            for (int q = 0; q < 4; q++) acc[i][j][q] = 0.f;

    const int nk = K / 64;
    // prologue: stages 0,1
#pragma unroll
    for (int s = 0; s < 2; s++) {
        fp8_load_chunk(usm + (unsigned)(s * STG8), A, W, m0, n0, K, s, t);
        asm volatile("cp.async.commit_group;");
    }

    for (int c = 0; c < nk; c++) {
        asm volatile("cp.async.wait_group 1;");
        __syncthreads();
        const unsigned base = usm + (unsigned)((c % 3) * STG8);
#pragma unroll
        for (int ks = 0; ks < 2; ks++) {
            unsigned af[2][4];
            unsigned bf[4][4];
#pragma unroll
            for (int i = 0; i < 2; i++)
                ldsm4(af[i][0], af[i][1], af[i][2], af[i][3],
                      base + aoff + (unsigned)(i * 16 * P8 + ks * 32));
#pragma unroll
            for (int j = 0; j < 4; j++)
                ldsm4(bf[j][0], bf[j][1], bf[j][2], bf[j][3],
                      base + boff + (unsigned)(j * 16 * P8 + ks * 32));
#pragma unroll
            for (int i = 0; i < 2; i++) {
#pragma unroll
                for (int j = 0; j < 4; j++) {
                    mma16832f8(acc[i][2 * j],     af[i], bf[j][0], bf[j][1]);
                    mma16832f8(acc[i][2 * j + 1], af[i], bf[j][2], bf[j][3]);
                }
            }
        }
        if (c + 2 < nk) {
            fp8_load_chunk(usm + (unsigned)(((c + 2) % 3) * STG8), A, W, m0, n0, K, c + 2, t);
        }
        asm volatile("cp.async.commit_group;");
    }

    // epilogue
#pragma unroll
    for (int i = 0; i < 2; i++) {
        int row = m0 + wm * 32 + i * 16 + (lane >> 2);
#pragma unroll
        for (int j = 0; j < 8; j++) {
            int col = n0 + wn * 64 + j * 8 + 2 * (lane & 3);
#pragma unroll
            for (int half = 0; half < 2; half++) {
                int r2 = row + half * 8;
                if (r2 >= M_) continue;
                float v0 = acc[i][j][half * 2 + 0] * INV64;
                float v1 = acc[i][j][half * 2 + 1] * INV64;
                size_t oidx = (size_t)r2 * Nc + col;
                if (MODE == 0) {
                    float x0, x1;
                    if (col < C_) {
                        x0 = (v0 + b0[col]) * 0.125f;
                        x1 = (v1 + b0[col + 1]) * 0.125f;
                    } else if (col < 2 * C_) {
                        x0 = v0;
                        x1 = v1;
                    } else {
                        x0 = v0 + b1[col - 2 * C_];
                        x1 = v1 + b1[col + 1 - 2 * C_];
                    }
                    __nv_bfloat162* op = (__nv_bfloat162*)((__nv_bfloat16*)outv + oidx);
                    *op = __floats2bfloat162_rn(x0, x1);
                } else if (MODE == 1) {
                    float2* op = (float2*)((float*)outv + oidx);
                    float2 cur = *op;
                    cur.x += b1[col]     * (v0 + b0[col]);
                    cur.y += b1[col + 1] * (v1 + b0[col + 1]);
                    *op = cur;
                } else {
                    float x0 = v0 + b0[col];
                    float x1 = v1 + b0[col + 1];
                    x0 = x0 * normcdff(x0);
                    x1 = x1 * normcdff(x1);
                    unsigned short p = (unsigned short)f2e4m3(x0)
                                     | ((unsigned short)f2e4m3(x1) << 8);
                    *(unsigned short*)((unsigned char*)outv + oidx) = p;
                }
            }
        }
    }
}

// ---------------- relative position bias ----------------
__global__ void relbias_kernel(const float* __restrict__ table, const int* __restrict__ ridx) {
    int i = blockIdx.x * 256 + threadIdx.x;
    if (i < NN_) {
        int id = ridx[i];
#pragma unroll
        for (int h = 0; h < H_; h++) g_bias[h * NN_ + i] = table[id * H_ + h];
    }
}

// ---------------- fused flash attention (bf16 HMMA), one block per (b,h) -----------
#define QK_PITCH 72
#define VT_PITCH 216
#define SM_Q 0
#define SM_K (208 * QK_PITCH)
#define SM_V (2 * 208 * QK_PITCH)
#define SM_TOT (2 * 208 * QK_PITCH + 64 * VT_PITCH)

__global__ __launch_bounds__(256) void attn_kernel(const __nv_bfloat16* __restrict__ qkv,
                                                   unsigned char* __restrict__ o) {
    extern __shared__ __nv_bfloat16 sm[];
    const int t = threadIdx.x;
    const int bh = blockIdx.x;
    const int b = bh / H_;
    const int h = bh % H_;

    {
        uint4 zz = make_uint4(0u, 0u, 0u, 0u);
        for (int i = t; i < SM_TOT / 8; i += 256) *(uint4*)&sm[i * 8] = zz;
    }
    __syncthreads();

    const __nv_bfloat16* base = qkv + (size_t)(b * N_) * (3 * C_) + h * D_;
    for (int i = t; i < N_ * 8; i += 256) {
        int row = i >> 3;
        int d8  = (i & 7) * 8;
        const __nv_bfloat16* rp = base + (size_t)row * (3 * C_);
        uint4 vq = *(const uint4*)(rp + d8);
        uint4 vk = *(const uint4*)(rp + C_ + d8);
        uint4 vv = *(const uint4*)(rp + 2 * C_ + d8);
        *(uint4*)&sm[SM_Q + row * QK_PITCH + d8] = vq;
        *(uint4*)&sm[SM_K + row * QK_PITCH + d8] = vk;
        __nv_bfloat16 tmp[8];
        *(uint4*)tmp = vv;
#pragma unroll
        for (int q = 0; q < 8; q++) sm[SM_V + (d8 + q) * VT_PITCH + row] = tmp[q];
    }
    __syncthreads();

    const int warp = t >> 5;
    const int lane = t & 31;
    const int g  = lane >> 3;
    const int rr = lane & 7;
    const unsigned usm = s2u(sm);
    const int arow = ((g & 1) << 3) + rr;
    const int acol = ((g >> 1) << 3);
    const int brow = ((g >> 1) << 3) + rr;
    const int bcol = ((g & 1) << 3);
    const int r0 = lane >> 2;
    const int cq = 2 * (lane & 3);
    const float* biasrow = g_bias + (size_t)h * NN_;

    for (int mt = warp; mt < 13; mt += 8) {
        const int R = mt * 16;
        unsigned aQ[4][4];
#pragma unroll
        for (int k = 0; k < 4; k++) {
            ldsm4(aQ[k][0], aQ[k][1], aQ[k][2], aQ[k][3],
                  usm + (unsigned)((SM_Q + (R + arow) * QK_PITCH + k * 16 + acol) * 2));
        }
        float S[26][4];
#pragma unroll
        for (int i = 0; i < 26; i++)
#pragma unroll
            for (int q = 0; q < 4; q++) S[i][q] = 0.f;
#pragma unroll
        for (int nt = 0; nt < 13; nt++) {
#pragma unroll
            for (int k = 0; k < 4; k++) {
                unsigned bk[4];
                ldsm4(bk[0], bk[1], bk[2], bk[3],
                      usm + (unsigned)((SM_K + (nt * 16 + brow) * QK_PITCH + k * 16 + bcol) * 2));
                mma16816(S[2 * nt],     aQ[k], bk[0], bk[1]);
                mma16816(S[2 * nt + 1], aQ[k], bk[2], bk[3]);
            }
        }
        const int gr0 = R + r0;
        const int gr1 = gr0 + 8;
        float mx0 = -1e30f, mx1 = -1e30f;
#pragma unroll
        for (int nt = 0; nt < 26; nt++) {
            int c0 = nt * 8 + cq;
            int c1 = c0 + 1;
            float b00 = (gr0 < N_ && c0 < N_) ? __ldg(biasrow + gr0 * N_ + c0) : 0.f;
            float b01 = (gr0 < N_ && c1 < N_) ? __ldg(biasrow + gr0 * N_ + c1) : 0.f;
            float b10 = (gr1 < N_ && c0 < N_) ? __ldg(biasrow + gr1 * N_ + c0) : 0.f;
            float b11 = (gr1 < N_ && c1 < N_) ? __ldg(biasrow + gr1 * N_ + c1) : 0.f;
            S[nt][0] = (c0 < N_) ? S[nt][0] + b00 : -1e30f;
            S[nt][1] = (c1 < N_) ? S[nt][1] + b01 : -1e30f;
            S[nt][2] = (c0 < N_) ? S[nt][2] + b10 : -1e30f;
            S[nt][3] = (c1 < N_) ? S[nt][3] + b11 : -1e30f;
            mx0 = fmaxf(mx0, fmaxf(S[nt][0], S[nt][1]));
            mx1 = fmaxf(mx1, fmaxf(S[nt][2], S[nt][3]));
        }
        mx0 = fmaxf(mx0, __shfl_xor_sync(0xffffffffu, mx0, 1));
        mx0 = fmaxf(mx0, __shfl_xor_sync(0xffffffffu, mx0, 2));
        mx1 = fmaxf(mx1, __shfl_xor_sync(0xffffffffu, mx1, 1));
        mx1 = fmaxf(mx1, __shfl_xor_sync(0xffffffffu, mx1, 2));
        float sum0 = 0.f, sum1 = 0.f;
#pragma unroll
        for (int nt = 0; nt < 26; nt++) {
            S[nt][0] = __expf(S[nt][0] - mx0);
            S[nt][1] = __expf(S[nt][1] - mx0);
            S[nt][2] = __expf(S[nt][2] - mx1);
            S[nt][3] = __expf(S[nt][3] - mx1);
            sum0 += S[nt][0] + S[nt][1];
            sum1 += S[nt][2] + S[nt][3];
        }
        sum0 += __shfl_xor_sync(0xffffffffu, sum0, 1);
        sum0 += __shfl_xor_sync(0xffffffffu, sum0, 2);
        sum1 += __shfl_xor_sync(0xffffffffu, sum1, 1);
        sum1 += __shfl_xor_sync(0xffffffffu, sum1, 2);

        float O[8][4];
#pragma unroll
        for (int i = 0; i < 8; i++)
#pragma unroll
            for (int q = 0; q < 4; q++) O[i][q] = 0.f;
#pragma unroll
        for (int kt = 0; kt < 13; kt++) {
            unsigned aP[4];
            aP[0] = packbf(S[2 * kt][0],     S[2 * kt][1]);
            aP[1] = packbf(S[2 * kt][2],     S[2 * kt][3]);
            aP[2] = packbf(S[2 * kt + 1][0], S[2 * kt + 1][1]);
            aP[3] = packbf(S[2 * kt + 1][2], S[2 * kt + 1][3]);
#pragma unroll
            for (int p = 0; p < 4; p++) {
                unsigned bv[4];
                ldsm4(bv[0], bv[1], bv[2], bv[3],
                      usm + (unsigned)((SM_V + (p * 16 + brow) * VT_PITCH + kt * 16 + bcol) * 2));
                mma16816(O[2 * p],     aP, bv[0], bv[1]);
                mma16816(O[2 * p + 1], aP, bv[2], bv[3]);
            }
        }
        float inv0 = 1.f / sum0;
        float inv1 = 1.f / sum1;
#pragma unroll
        for (int dt = 0; dt < 8; dt++) {
            int col = h * D_ + dt * 8 + cq;
            if (gr0 < N_) {
                unsigned short p = (unsigned short)f2e4m3(O[dt][0] * inv0)
                                 | ((unsigned short)f2e4m3(O[dt][1] * inv0) << 8);
                *(unsigned short*)&o[(size_t)(b * N_ + gr0) * C_ + col] = p;
            }
            if (gr1 < N_) {
                unsigned short p = (unsigned short)f2e4m3(O[dt][2] * inv1)
                                 | ((unsigned short)f2e4m3(O[dt][3] * inv1) << 8);
                *(unsigned short*)&o[(size_t)(b * N_ + gr1) * C_ + col] = p;
            }
        }
    }
}

// ---------------- launch ----------------
extern "C" void kernel_launch(void* const* d_in, const int* in_sizes, int n_in,
                              void* d_out, int out_size) {
    const float* x      = (const float*)d_in[0];
    const float* qkv_w  = (const float*)d_in[1];
    const float* q_bias = (const float*)d_in[2];
    const float* v_bias = (const float*)d_in[3];
    const float* proj_w = (const float*)d_in[4];
    const float* proj_b = (const float*)d_in[5];
    const float* ln1_s  = (const float*)d_in[6];
    const float* ln1_b  = (const float*)d_in[7];
    const float* ln2_s  = (const float*)d_in[8];
    const float* ln2_b  = (const float*)d_in[9];
    const float* fc1_w  = (const float*)d_in[10];
    const float* fc1_b  = (const float*)d_in[11];
    const float* fc2_w  = (const float*)d_in[12];
    const float* fc2_b  = (const float*)d_in[13];
    const float* gamma1 = (const float*)d_in[14];
    const float* gamma2 = (const float*)d_in[15];
    const float* rtab   = (const float*)d_in[16];
    const int*   ridx   = (const int*)d_in[17];
    float* h = (float*)d_out;

    void* pz = 0;
    void* pqkv = 0;
    void* po = 0;
    void* pmlp = 0;
    void* pw = 0;
    cudaGetSymbolAddress(&pz, g_z);
    cudaGetSymbolAddress(&pqkv, g_qkvb);
    cudaGetSymbolAddress(&po, g_o);
    cudaGetSymbolAddress(&pmlp, g_mlp);
    cudaGetSymbolAddress(&pw, g_wbf);
    unsigned char* z    = (unsigned char*)pz;
    __nv_bfloat16* qkvb = (__nv_bfloat16*)pqkv;
    unsigned char* o    = (unsigned char*)po;
    unsigned char* mlp  = (unsigned char*)pmlp;
    unsigned char* wbf  = (unsigned char*)pw;

    const int attn_smem = SM_TOT * 2;
    cudaFuncSetAttribute(attn_kernel, cudaFuncAttributeMaxDynamicSharedMemorySize, attn_smem);
    cudaFuncSetAttribute(fp8_gemm<0>, cudaFuncAttributeMaxDynamicSharedMemorySize, SMEM8);
    cudaFuncSetAttribute(fp8_gemm<1>, cudaFuncAttributeMaxDynamicSharedMemorySize, SMEM8);
    cudaFuncSetAttribute(fp8_gemm<2>, cudaFuncAttributeMaxDynamicSharedMemorySize, SMEM8);

    cudaMemcpyAsync(h, x, sizeof(float) * (size_t)M_ * C_, cudaMemcpyDeviceToDevice);
    relbias_kernel<<<(NN_ + 255) / 256, 256>>>(rtab, ridx);

    {
        int pq = 3 * C_ * C_;
        int pp = C_ * C_;
        int p1 = FF_ * C_;
        int p2 = C_ * FF_;
        int tq = DEPTH_ * pq / 4;
        int tp = DEPTH_ * pp / 4;
        int t1 = DEPTH_ * p1 / 4;
        int t2 = DEPTH_ * p2 / 4;
        cvtw_kernel<<<(tq + 255) / 256, 256>>>(qkv_w,  pq, W_QKV_OFF,  tq);
        cvtw_kernel<<<(tp + 255) / 256, 256>>>(proj_w, pp, W_PROJ_OFF, tp);
        cvtw_kernel<<<(t1 + 255) / 256, 256>>>(fc1_w,  p1, W_FC1_OFF,  t1);
        cvtw_kernel<<<(t2 + 255) / 256, 256>>>(fc2_w,  p2, W_FC2_OFF,  t2);
    }

    const int mtiles = 99;  // 99*128 = 12672 >= 12608
    for (int l = 0; l < DEPTH_; l++) {
        const unsigned char* wl = wbf + (size_t)l * W_LSTRIDE;
        ln_kernel<<<M_, 256>>>(h, ln1_s + l * C_, ln1_b + l * C_, z);
        fp8_gemm<0><<<dim3(3 * C_ / 256, mtiles), 512, SMEM8>>>(
            z, wl + W_QKV_OFF, (void*)qkvb, q_bias + l * C_, v_bias + l * C_, 3 * C_, C_);
        attn_kernel<<<B_ * H_, 256, attn_smem>>>(qkvb, o);
        fp8_gemm<1><<<dim3(C_ / 256, mtiles), 512, SMEM8>>>(
            o, wl + W_PROJ_OFF, (void*)h, proj_b + l * C_, gamma1 + l * C_, C_, C_);
        ln_kernel<<<M_, 256>>>(h, ln2_s + l * C_, ln2_b + l * C_, z);
        fp8_gemm<2><<<dim3(FF_ / 256, mtiles), 512, SMEM8>>>(
            z, wl + W_FC1_OFF, (void*)mlp, fc1_b + l * FF_, (const float*)0, FF_, C_);
        fp8_gemm<1><<<dim3(C_ / 256, mtiles), 512, SMEM8>>>(
            mlp, wl + W_FC2_OFF, (void*)h, fc2_b + l * C_, gamma2 + l * C_, C_, FF_);
    }
}

// round 9
// speedup vs baseline: 9.7839x; 1.0339x over previous
#include <cuda_runtime.h>
#include <cuda_bf16.h>
#include <cuda_fp8.h>
#include <cstdint>
#include <cstddef>
#include <math.h>

#define B_     64
#define N_     197
#define C_     768
#define H_     12
#define D_     64
#define FF_    3072
#define DEPTH_ 12
#define M_     (B_ * N_)
#define NN_    (N_ * N_)
#define M_PAD  12672                 // 99 tiles of 128

#define W_QKV_OFF  0
#define W_PROJ_OFF (3 * C_ * C_)
#define W_FC1_OFF  (W_PROJ_OFF + C_ * C_)
#define W_FC2_OFF  (W_FC1_OFF + FF_ * C_)
#define W_LSTRIDE  (W_FC2_OFF + C_ * FF_)

#define WSCALE   64.0f
#define INV64    0.015625f

// ---------------- scratch (device globals; zero-initialized) ----------------
__device__ unsigned char g_z[(size_t)M_PAD * C_];          // LN out (e4m3)
__device__ __nv_bfloat16 g_qkvb[(size_t)M_PAD * 3 * C_];   // qkv (bf16, q pre-scaled)
__device__ unsigned char g_o[(size_t)M_PAD * C_];          // attn out (e4m3)
__device__ unsigned char g_mlp[(size_t)M_PAD * FF_];       // MLP hidden (e4m3)
__device__ float         g_bias[H_ * NN_];
__device__ unsigned char g_wbf[(size_t)DEPTH_ * W_LSTRIDE];// weights (e4m3, x64)

// ---------------- helpers ----------------
__device__ __forceinline__ float warp_sum(float v) {
#pragma unroll
    for (int o = 16; o > 0; o >>= 1) v += __shfl_xor_sync(0xffffffffu, v, o);
    return v;
}
__device__ __forceinline__ unsigned s2u(const void* p) {
    return (unsigned)__cvta_generic_to_shared(p);
}
__device__ __forceinline__ void ldsm4(unsigned& r0, unsigned& r1, unsigned& r2, unsigned& r3,
                                      unsigned addr) {
    asm volatile("ldmatrix.sync.aligned.m8n8.x4.shared.b16 {%0,%1,%2,%3}, [%4];"
                 : "=r"(r0), "=r"(r1), "=r"(r2), "=r"(r3)
                 : "r"(addr));
}
__device__ __forceinline__ void mma16816(float* c, const unsigned* a, unsigned b0, unsigned b1) {
    asm volatile(
        "mma.sync.aligned.m16n8k16.row.col.f32.bf16.bf16.f32 "
        "{%0,%1,%2,%3}, {%4,%5,%6,%7}, {%8,%9}, {%0,%1,%2,%3};"
        : "+f"(c[0]), "+f"(c[1]), "+f"(c[2]), "+f"(c[3])
        : "r"(a[0]), "r"(a[1]), "r"(a[2]), "r"(a[3]), "r"(b0), "r"(b1));
}
__device__ __forceinline__ void mma16832f8(float* c, const unsigned* a, unsigned b0, unsigned b1) {
    asm volatile(
        "mma.sync.aligned.m16n8k32.row.col.f32.e4m3.e4m3.f32 "
        "{%0,%1,%2,%3}, {%4,%5,%6,%7}, {%8,%9}, {%0,%1,%2,%3};"
        : "+f"(c[0]), "+f"(c[1]), "+f"(c[2]), "+f"(c[3])
        : "r"(a[0]), "r"(a[1]), "r"(a[2]), "r"(a[3]), "r"(b0), "r"(b1));
}
__device__ __forceinline__ unsigned packbf(float x, float y) {
    __nv_bfloat162 t = __floats2bfloat162_rn(x, y);
    return *(unsigned*)&t;
}
__device__ __forceinline__ void cpa16(unsigned saddr, const void* g) {
    asm volatile("cp.async.ca.shared.global [%0], [%1], 16;" :: "r"(saddr), "l"(g));
}
__device__ __forceinline__ unsigned char f2e4m3(float x) {
    return (unsigned char)__nv_cvt_float_to_fp8(x, __NV_SATFINITE, __NV_E4M3);
}

// ---------------- weight fp32 -> e4m3 (x64) ----------------
__global__ void cvtw_kernel(const float* __restrict__ src, int per_layer,
                            int toff, int total4) {
    int i = blockIdx.x * 256 + threadIdx.x;
    if (i >= total4) return;
    int e = i * 4;
    int l = e / per_layer;
    int w = e % per_layer;
    float4 v = *(const float4*)(src + e);
    unsigned char* d = g_wbf + (size_t)l * W_LSTRIDE + toff + w;
    d[0] = f2e4m3(v.x * WSCALE);
    d[1] = f2e4m3(v.y * WSCALE);
    d[2] = f2e4m3(v.z * WSCALE);
    d[3] = f2e4m3(v.w * WSCALE);
}

// ---------------- LayerNorm -> e4m3 ----------------
__global__ __launch_bounds__(256) void ln_kernel(const float* __restrict__ x,
                                                 const float* __restrict__ s,
                                                 const float* __restrict__ bsh,
                                                 unsigned char* __restrict__ z) {
    int row = blockIdx.x;
    const float* xr = x + (size_t)row * C_;
    float v0 = xr[threadIdx.x];
    float v1 = xr[threadIdx.x + 256];
    float v2 = xr[threadIdx.x + 512];
    float sum = v0 + v1 + v2;
    float sq  = v0 * v0 + v1 * v1 + v2 * v2;
    sum = warp_sum(sum);
    sq  = warp_sum(sq);
    __shared__ float sh1[8];
    __shared__ float sh2[8];
    int w = threadIdx.x >> 5;
    int lane = threadIdx.x & 31;
    if (lane == 0) { sh1[w] = sum; sh2[w] = sq; }
    __syncthreads();
    if (w == 0) {
        float a  = (lane < 8) ? sh1[lane] : 0.f;
        float b2 = (lane < 8) ? sh2[lane] : 0.f;
        a  = warp_sum(a);
        b2 = warp_sum(b2);
        if (lane == 0) { sh1[0] = a; sh2[0] = b2; }
    }
    __syncthreads();
    float mean = sh1[0] * (1.f / C_);
    float var  = sh2[0] * (1.f / C_) - mean * mean;
    float r    = rsqrtf(var + 1e-5f);
    int c0 = threadIdx.x;
    z[(size_t)row * C_ + c0]       = f2e4m3((v0 - mean) * r * s[c0]       + bsh[c0]);
    z[(size_t)row * C_ + c0 + 256] = f2e4m3((v1 - mean) * r * s[c0 + 256] + bsh[c0 + 256]);
    z[(size_t)row * C_ + c0 + 512] = f2e4m3((v2 - mean) * r * s[c0 + 512] + bsh[c0 + 512]);
}

// ---------------- FP8 mma.sync GEMM v2 ----------------
// out[M,Nc] = A[M,K](e4m3) @ (64*W)[Nc,K](e4m3)^T / 64 + epilogue
// BM=128 BN=128 BK=64(bytes), 256 threads (8 warps 4x2), warp tile 32x64,
// 4-stage cp.async pipeline, smem pitch 80B, 2 CTAs/SM.
// MODE 0: bf16 out = (acc/64 + q_bias)*0.125 | acc/64 | acc/64 + v_bias
// MODE 1: fp32 out += b1[col]*(acc/64 + b0[col])
// MODE 2: e4m3 out = gelu(acc/64 + b0[col])
#define P8      80
#define STG8_A  (128 * P8)              // 10240 B
#define STG8    (STG8_A + 128 * P8)     // 20480 B
#define NSTG    4
#define SMEM8   (NSTG * STG8)           // 81920 B

__device__ __forceinline__ void fp8_load_chunk(unsigned base,
                                               const unsigned char* A,
                                               const unsigned char* W,
                                               int m0, int n0, int K, int c, int t) {
    const int cc = c * 64;
#pragma unroll
    for (int i = 0; i < 2; i++) {
        int idx = i * 256 + t;
        int row = idx >> 2;
        int seg = (idx & 3) * 16;
        cpa16(base + (unsigned)(row * P8 + seg), A + (size_t)(m0 + row) * K + cc + seg);
    }
#pragma unroll
    for (int i = 0; i < 2; i++) {
        int idx = i * 256 + t;
        int row = idx >> 2;
        int seg = (idx & 3) * 16;
        cpa16(base + (unsigned)(STG8_A + row * P8 + seg),
              W + (size_t)(n0 + row) * K + cc + seg);
    }
}

template <int MODE>
__global__ __launch_bounds__(256, 2) void fp8_gemm(const unsigned char* __restrict__ A,
                                                   const unsigned char* __restrict__ W,
                                                   void* __restrict__ outv,
                                                   const float* __restrict__ b0,
                                                   const float* __restrict__ b1,
                                                   int Nc, int K) {
    extern __shared__ unsigned char sm8[];
    const int t = threadIdx.x;
    const int warp = t >> 5;
    const int lane = t & 31;
    const int wm = warp >> 1;       // 0..3
    const int wn = warp & 1;        // 0..1
    const int m0 = blockIdx.y * 128;
    const int n0 = blockIdx.x * 128;
    const unsigned usm = s2u(sm8);

    const int g  = lane >> 3;
    const int rr = lane & 7;
    const unsigned aoff = (unsigned)((wm * 32 + ((g & 1) << 3) + rr) * P8 + (g >> 1) * 16);
    const unsigned boff = (unsigned)(STG8_A + (wn * 64 + ((g >> 1) << 3) + rr) * P8 + (g & 1) * 16);

    float acc[2][8][4];
#pragma unroll
    for (int i = 0; i < 2; i++)
#pragma unroll
        for (int j = 0; j < 8; j++)
#pragma unroll
            for (int q = 0; q < 4; q++) acc[i][j][q] = 0.f;

    const int nk = K / 64;
    // prologue: stages 0,1,2
#pragma unroll
    for (int s = 0; s < 3; s++) {
        fp8_load_chunk(usm + (unsigned)(s * STG8), A, W, m0, n0, K, s, t);
        asm volatile("cp.async.commit_group;");
    }

    for (int c = 0; c < nk; c++) {
        asm volatile("cp.async.wait_group 2;");
        __syncthreads();
        const unsigned base = usm + (unsigned)((c % NSTG) * STG8);
#pragma unroll
        for (int ks = 0; ks < 2; ks++) {
            unsigned af[2][4];
            unsigned bf[4][4];
#pragma unroll
            for (int i = 0; i < 2; i++)
                ldsm4(af[i][0], af[i][1], af[i][2], af[i][3],
                      base + aoff + (unsigned)(i * 16 * P8 + ks * 32));
#pragma unroll
            for (int j = 0; j < 4; j++)
                ldsm4(bf[j][0], bf[j][1], bf[j][2], bf[j][3],
                      base + boff + (unsigned)(j * 16 * P8 + ks * 32));
#pragma unroll
            for (int i = 0; i < 2; i++) {
#pragma unroll
                for (int j = 0; j < 4; j++) {
                    mma16832f8(acc[i][2 * j],     af[i], bf[j][0], bf[j][1]);
                    mma16832f8(acc[i][2 * j + 1], af[i], bf[j][2], bf[j][3]);
                }
            }
        }
        if (c + 3 < nk) {
            fp8_load_chunk(usm + (unsigned)(((c + 3) % NSTG) * STG8), A, W, m0, n0, K, c + 3, t);
        }
        asm volatile("cp.async.commit_group;");
    }

    // epilogue
#pragma unroll
    for (int i = 0; i < 2; i++) {
        int row = m0 + wm * 32 + i * 16 + (lane >> 2);
#pragma unroll
        for (int j = 0; j < 8; j++) {
            int col = n0 + wn * 64 + j * 8 + 2 * (lane & 3);
#pragma unroll
            for (int half = 0; half < 2; half++) {
                int r2 = row + half * 8;
                if (r2 >= M_) continue;
                float v0 = acc[i][j][half * 2 + 0] * INV64;
                float v1 = acc[i][j][half * 2 + 1] * INV64;
                size_t oidx = (size_t)r2 * Nc + col;
                if (MODE == 0) {
                    float x0, x1;
                    if (col < C_) {
                        x0 = (v0 + b0[col]) * 0.125f;
                        x1 = (v1 + b0[col + 1]) * 0.125f;
                    } else if (col < 2 * C_) {
                        x0 = v0;
                        x1 = v1;
                    } else {
                        x0 = v0 + b1[col - 2 * C_];
                        x1 = v1 + b1[col + 1 - 2 * C_];
                    }
                    __nv_bfloat162* op = (__nv_bfloat162*)((__nv_bfloat16*)outv + oidx);
                    *op = __floats2bfloat162_rn(x0, x1);
                } else if (MODE == 1) {
                    float2* op = (float2*)((float*)outv + oidx);
                    float2 cur = *op;
                    cur.x += b1[col]     * (v0 + b0[col]);
                    cur.y += b1[col + 1] * (v1 + b0[col + 1]);
                    *op = cur;
                } else {
                    float x0 = v0 + b0[col];
                    float x1 = v1 + b0[col + 1];
                    x0 = x0 * normcdff(x0);
                    x1 = x1 * normcdff(x1);
                    unsigned short p = (unsigned short)f2e4m3(x0)
                                     | ((unsigned short)f2e4m3(x1) << 8);
                    *(unsigned short*)((unsigned char*)outv + oidx) = p;
                }
            }
        }
    }
}

// ---------------- relative position bias ----------------
__global__ void relbias_kernel(const float* __restrict__ table, const int* __restrict__ ridx) {
    int i = blockIdx.x * 256 + threadIdx.x;
    if (i < NN_) {
        int id = ridx[i];
#pragma unroll
        for (int h = 0; h < H_; h++) g_bias[h * NN_ + i] = table[id * H_ + h];
    }
}

// ---------------- fused flash attention (bf16 HMMA), one block per (b,h) -----------
#define QK_PITCH 72
#define VT_PITCH 216
#define SM_Q 0
#define SM_K (208 * QK_PITCH)
#define SM_V (2 * 208 * QK_PITCH)
#define SM_TOT (2 * 208 * QK_PITCH + 64 * VT_PITCH)

__global__ __launch_bounds__(256) void attn_kernel(const __nv_bfloat16* __restrict__ qkv,
                                                   unsigned char* __restrict__ o) {
    extern __shared__ __nv_bfloat16 sm[];
    const int t = threadIdx.x;
    const int bh = blockIdx.x;
    const int b = bh / H_;
    const int h = bh % H_;

    {
        uint4 zz = make_uint4(0u, 0u, 0u, 0u);
        for (int i = t; i < SM_TOT / 8; i += 256) *(uint4*)&sm[i * 8] = zz;
    }
    __syncthreads();

    const __nv_bfloat16* base = qkv + (size_t)(b * N_) * (3 * C_) + h * D_;
    for (int i = t; i < N_ * 8; i += 256) {
        int row = i >> 3;
        int d8  = (i & 7) * 8;
        const __nv_bfloat16* rp = base + (size_t)row * (3 * C_);
        uint4 vq = *(const uint4*)(rp + d8);
        uint4 vk = *(const uint4*)(rp + C_ + d8);
        uint4 vv = *(const uint4*)(rp + 2 * C_ + d8);
        *(uint4*)&sm[SM_Q + row * QK_PITCH + d8] = vq;
        *(uint4*)&sm[SM_K + row * QK_PITCH + d8] = vk;
        __nv_bfloat16 tmp[8];
        *(uint4*)tmp = vv;
#pragma unroll
        for (int q = 0; q < 8; q++) sm[SM_V + (d8 + q) * VT_PITCH + row] = tmp[q];
    }
    __syncthreads();

    const int warp = t >> 5;
    const int lane = t & 31;
    const int g  = lane >> 3;
    const int rr = lane & 7;
    const unsigned usm = s2u(sm);
    const int arow = ((g & 1) << 3) + rr;
    const int acol = ((g >> 1) << 3);
    const int brow = ((g >> 1) << 3) + rr;
    const int bcol = ((g & 1) << 3);
    const int r0 = lane >> 2;
    const int cq = 2 * (lane & 3);
    const float* biasrow = g_bias + (size_t)h * NN_;

    for (int mt = warp; mt < 13; mt += 8) {
        const int R = mt * 16;
        unsigned aQ[4][4];
#pragma unroll
        for (int k = 0; k < 4; k++) {
            ldsm4(aQ[k][0], aQ[k][1], aQ[k][2], aQ[k][3],
                  usm + (unsigned)((SM_Q + (R + arow) * QK_PITCH + k * 16 + acol) * 2));
        }
        float S[26][4];
#pragma unroll
        for (int i = 0; i < 26; i++)
#pragma unroll
            for (int q = 0; q < 4; q++) S[i][q] = 0.f;
#pragma unroll
        for (int nt = 0; nt < 13; nt++) {
#pragma unroll
            for (int k = 0; k < 4; k++) {
                unsigned bk[4];
                ldsm4(bk[0], bk[1], bk[2], bk[3],
                      usm + (unsigned)((SM_K + (nt * 16 + brow) * QK_PITCH + k * 16 + bcol) * 2));
                mma16816(S[2 * nt],     aQ[k], bk[0], bk[1]);
                mma16816(S[2 * nt + 1], aQ[k], bk[2], bk[3]);
            }
        }
        const int gr0 = R + r0;
        const int gr1 = gr0 + 8;
        float mx0 = -1e30f, mx1 = -1e30f;
#pragma unroll
        for (int nt = 0; nt < 26; nt++) {
            int c0 = nt * 8 + cq;
            int c1 = c0 + 1;
            float b00 = (gr0 < N_ && c0 < N_) ? __ldg(biasrow + gr0 * N_ + c0) : 0.f;
            float b01 = (gr0 < N_ && c1 < N_) ? __ldg(biasrow + gr0 * N_ + c1) : 0.f;
            float b10 = (gr1 < N_ && c0 < N_) ? __ldg(biasrow + gr1 * N_ + c0) : 0.f;
            float b11 = (gr1 < N_ && c1 < N_) ? __ldg(biasrow + gr1 * N_ + c1) : 0.f;
            S[nt][0] = (c0 < N_) ? S[nt][0] + b00 : -1e30f;
            S[nt][1] = (c1 < N_) ? S[nt][1] + b01 : -1e30f;
            S[nt][2] = (c0 < N_) ? S[nt][2] + b10 : -1e30f;
            S[nt][3] = (c1 < N_) ? S[nt][3] + b11 : -1e30f;
            mx0 = fmaxf(mx0, fmaxf(S[nt][0], S[nt][1]));
            mx1 = fmaxf(mx1, fmaxf(S[nt][2], S[nt][3]));
        }
        mx0 = fmaxf(mx0, __shfl_xor_sync(0xffffffffu, mx0, 1));
        mx0 = fmaxf(mx0, __shfl_xor_sync(0xffffffffu, mx0, 2));
        mx1 = fmaxf(mx1, __shfl_xor_sync(0xffffffffu, mx1, 1));
        mx1 = fmaxf(mx1, __shfl_xor_sync(0xffffffffu, mx1, 2));
        float sum0 = 0.f, sum1 = 0.f;
#pragma unroll
        for (int nt = 0; nt < 26; nt++) {
            S[nt][0] = __expf(S[nt][0] - mx0);
            S[nt][1] = __expf(S[nt][1] - mx0);
            S[nt][2] = __expf(S[nt][2] - mx1);
            S[nt][3] = __expf(S[nt][3] - mx1);
            sum0 += S[nt][0] + S[nt][1];
            sum1 += S[nt][2] + S[nt][3];
        }
        sum0 += __shfl_xor_sync(0xffffffffu, sum0, 1);
        sum0 += __shfl_xor_sync(0xffffffffu, sum0, 2);
        sum1 += __shfl_xor_sync(0xffffffffu, sum1, 1);
        sum1 += __shfl_xor_sync(0xffffffffu, sum1, 2);

        float O[8][4];
#pragma unroll
        for (int i = 0; i < 8; i++)
#pragma unroll
            for (int q = 0; q < 4; q++) O[i][q] = 0.f;
#pragma unroll
        for (int kt = 0; kt < 13; kt++) {
            unsigned aP[4];
            aP[0] = packbf(S[2 * kt][0],     S[2 * kt][1]);
            aP[1] = packbf(S[2 * kt][2],     S[2 * kt][3]);
            aP[2] = packbf(S[2 * kt + 1][0], S[2 * kt + 1][1]);
            aP[3] = packbf(S[2 * kt + 1][2], S[2 * kt + 1][3]);
#pragma unroll
            for (int p = 0; p < 4; p++) {
                unsigned bv[4];
                ldsm4(bv[0], bv[1], bv[2], bv[3],
                      usm + (unsigned)((SM_V + (p * 16 + brow) * VT_PITCH + kt * 16 + bcol) * 2));
                mma16816(O[2 * p],     aP, bv[0], bv[1]);
                mma16816(O[2 * p + 1], aP, bv[2], bv[3]);
            }
        }
        float inv0 = 1.f / sum0;
        float inv1 = 1.f / sum1;
#pragma unroll
        for (int dt = 0; dt < 8; dt++) {
            int col = h * D_ + dt * 8 + cq;
            if (gr0 < N_) {
                unsigned short p = (unsigned short)f2e4m3(O[dt][0] * inv0)
                                 | ((unsigned short)f2e4m3(O[dt][1] * inv0) << 8);
                *(unsigned short*)&o[(size_t)(b * N_ + gr0) * C_ + col] = p;
            }
            if (gr1 < N_) {
                unsigned short p = (unsigned short)f2e4m3(O[dt][2] * inv1)
                                 | ((unsigned short)f2e4m3(O[dt][3] * inv1) << 8);
                *(unsigned short*)&o[(size_t)(b * N_ + gr1) * C_ + col] = p;
            }
        }
    }
}

// ---------------- launch ----------------
extern "C" void kernel_launch(void* const* d_in, const int* in_sizes, int n_in,
                              void* d_out, int out_size) {
    const float* x      = (const float*)d_in[0];
    const float* qkv_w  = (const float*)d_in[1];
    const float* q_bias = (const float*)d_in[2];
    const float* v_bias = (const float*)d_in[3];
    const float* proj_w = (const float*)d_in[4];
    const float* proj_b = (const float*)d_in[5];
    const float* ln1_s  = (const float*)d_in[6];
    const float* ln1_b  = (const float*)d_in[7];
    const float* ln2_s  = (const float*)d_in[8];
    const float* ln2_b  = (const float*)d_in[9];
    const float* fc1_w  = (const float*)d_in[10];
    const float* fc1_b  = (const float*)d_in[11];
    const float* fc2_w  = (const float*)d_in[12];
    const float* fc2_b  = (const float*)d_in[13];
    const float* gamma1 = (const float*)d_in[14];
    const float* gamma2 = (const float*)d_in[15];
    const float* rtab   = (const float*)d_in[16];
    const int*   ridx   = (const int*)d_in[17];
    float* h = (float*)d_out;

    void* pz = 0;
    void* pqkv = 0;
    void* po = 0;
    void* pmlp = 0;
    void* pw = 0;
    cudaGetSymbolAddress(&pz, g_z);
    cudaGetSymbolAddress(&pqkv, g_qkvb);
    cudaGetSymbolAddress(&po, g_o);
    cudaGetSymbolAddress(&pmlp, g_mlp);
    cudaGetSymbolAddress(&pw, g_wbf);
    unsigned char* z    = (unsigned char*)pz;
    __nv_bfloat16* qkvb = (__nv_bfloat16*)pqkv;
    unsigned char* o    = (unsigned char*)po;
    unsigned char* mlp  = (unsigned char*)pmlp;
    unsigned char* wbf  = (unsigned char*)pw;

    const int attn_smem = SM_TOT * 2;
    cudaFuncSetAttribute(attn_kernel, cudaFuncAttributeMaxDynamicSharedMemorySize, attn_smem);
    cudaFuncSetAttribute(fp8_gemm<0>, cudaFuncAttributeMaxDynamicSharedMemorySize, SMEM8);
    cudaFuncSetAttribute(fp8_gemm<1>, cudaFuncAttributeMaxDynamicSharedMemorySize, SMEM8);
    cudaFuncSetAttribute(fp8_gemm<2>, cudaFuncAttributeMaxDynamicSharedMemorySize, SMEM8);

    cudaMemcpyAsync(h, x, sizeof(float) * (size_t)M_ * C_, cudaMemcpyDeviceToDevice);
    relbias_kernel<<<(NN_ + 255) / 256, 256>>>(rtab, ridx);

    {
        int pq = 3 * C_ * C_;
        int pp = C_ * C_;
        int p1 = FF_ * C_;
        int p2 = C_ * FF_;
        int tq = DEPTH_ * pq / 4;
        int tp = DEPTH_ * pp / 4;
        int t1 = DEPTH_ * p1 / 4;
        int t2 = DEPTH_ * p2 / 4;
        cvtw_kernel<<<(tq + 255) / 256, 256>>>(qkv_w,  pq, W_QKV_OFF,  tq);
        cvtw_kernel<<<(tp + 255) / 256, 256>>>(proj_w, pp, W_PROJ_OFF, tp);
        cvtw_kernel<<<(t1 + 255) / 256, 256>>>(fc1_w,  p1, W_FC1_OFF,  t1);
        cvtw_kernel<<<(t2 + 255) / 256, 256>>>(fc2_w,  p2, W_FC2_OFF,  t2);
    }

    const int mtiles = 99;  // 99*128 = 12672 >= 12608
    for (int l = 0; l < DEPTH_; l++) {
        const unsigned char* wl = wbf + (size_t)l * W_LSTRIDE;
        ln_kernel<<<M_, 256>>>(h, ln1_s + l * C_, ln1_b + l * C_, z);
        fp8_gemm<0><<<dim3(3 * C_ / 128, mtiles), 256, SMEM8>>>(
            z, wl + W_QKV_OFF, (void*)qkvb, q_bias + l * C_, v_bias + l * C_, 3 * C_, C_);
        attn_kernel<<<B_ * H_, 256, attn_smem>>>(qkvb, o);
        fp8_gemm<1><<<dim3(C_ / 128, mtiles), 256, SMEM8>>>(
            o, wl + W_PROJ_OFF, (void*)h, proj_b + l * C_, gamma1 + l * C_, C_, C_);
        ln_kernel<<<M_, 256>>>(h, ln2_s + l * C_, ln2_b + l * C_, z);
        fp8_gemm<2><<<dim3(FF_ / 128, mtiles), 256, SMEM8>>>(
            z, wl + W_FC1_OFF, (void*)mlp, fc1_b + l * FF_, (const float*)0, FF_, C_);
        fp8_gemm<1><<<dim3(C_ / 128, mtiles), 256, SMEM8>>>(
            mlp, wl + W_FC2_OFF, (void*)h, fc2_b + l * C_, gamma2 + l * C_, C_, FF_);
    }
}